// round 1
// baseline (speedup 1.0000x reference)
#include <cuda_runtime.h>
#include <math.h>

#define ED   1024      // embed dim
#define NH   16        // heads
#define HD   64        // head dim
#define SEQ  2048
#define BATCH 2
#define MTOT (BATCH*SEQ)   // 4096 rows

// Scratch (allocation-free rule: __device__ globals)
__device__ float g_Q[MTOT * ED];
__device__ float g_K[MTOT * ED];
__device__ float g_V[MTOT * ED];
__device__ float g_C[MTOT * ED];

// ---------------------------------------------------------------------------
// GEMM: C[M,N] = (A (+ A2)) @ W[K,N] + bias[N]
// 64x64 tile, BK=16, 256 threads, 4x4 per thread.
// ---------------------------------------------------------------------------
template <bool ADD>
__global__ void __launch_bounds__(256)
gemm_bias(const float* __restrict__ A, const float* __restrict__ A2,
          const float* __restrict__ W, const float* __restrict__ bias,
          float* __restrict__ C, int M, int N, int K)
{
    __shared__ float As[16][64];   // [k][m]
    __shared__ float Bs[16][64];   // [k][n]

    const int tid = threadIdx.x;
    const int tx  = tid & 15;      // n-group
    const int ty  = tid >> 4;      // m-group
    const int mrow0 = blockIdx.y * 64;
    const int ncol0 = blockIdx.x * 64;

    float acc[4][4] = {};

    for (int k0 = 0; k0 < K; k0 += 16) {
        // A tile: 64 rows x 16 k
        #pragma unroll
        for (int i = tid; i < 64 * 16; i += 256) {
            int r = i >> 4, c = i & 15;
            float v = A[(size_t)(mrow0 + r) * K + k0 + c];
            if (ADD) v += A2[(size_t)(mrow0 + r) * K + k0 + c];
            As[c][r] = v;
        }
        // W tile: 16 k x 64 cols (coalesced)
        #pragma unroll
        for (int i = tid; i < 16 * 64; i += 256) {
            int r = i >> 6, c = i & 63;
            Bs[r][c] = W[(size_t)(k0 + r) * N + ncol0 + c];
        }
        __syncthreads();

        #pragma unroll
        for (int kk = 0; kk < 16; kk++) {
            float ra[4], rb[4];
            #pragma unroll
            for (int i = 0; i < 4; i++) ra[i] = As[kk][ty * 4 + i];
            #pragma unroll
            for (int j = 0; j < 4; j++) rb[j] = Bs[kk][tx * 4 + j];
            #pragma unroll
            for (int i = 0; i < 4; i++)
                #pragma unroll
                for (int j = 0; j < 4; j++)
                    acc[i][j] += ra[i] * rb[j];
        }
        __syncthreads();
    }

    #pragma unroll
    for (int i = 0; i < 4; i++) {
        int r = mrow0 + ty * 4 + i;
        #pragma unroll
        for (int j = 0; j < 4; j++) {
            int c = ncol0 + tx * 4 + j;
            C[(size_t)r * N + c] = acc[i][j] + bias[c];
        }
    }
}

// ---------------------------------------------------------------------------
// Flash-style attention. One CTA per (64-query tile, head, batch).
// sQ/sKP/sV = 3 x 16 KB = exactly 48 KB static smem.
// XOR swizzle (d ^ (row&31)) makes K^T / V column reads conflict-free at
// pitch 64 (padding would exceed the 48 KB static limit).
// ---------------------------------------------------------------------------
#define SW(r, d) ((d) ^ ((r) & 31))

__global__ void __launch_bounds__(256)
attn_kernel(const float* __restrict__ Q, const float* __restrict__ K,
            const float* __restrict__ V, float* __restrict__ ctx)
{
    __shared__ float sQ [64][64];  // [q][d]    (rows broadcast-read, no swizzle)
    __shared__ float sKP[64][64];  // K: [k][d] swizzled; later reused as P [q][k]
    __shared__ float sV [64][64];  // [k][d] swizzled

    const int qt  = blockIdx.x;
    const int h   = blockIdx.y;
    const int b   = blockIdx.z;
    const int tid = threadIdx.x;
    const int tx  = tid & 15;
    const int ty  = tid >> 4;

    const float scale = 0.125f;            // 1/sqrt(64)
    const int qrow0 = b * SEQ + qt * 64;
    const int coff  = h * HD;

    // Load Q tile, pre-scaled
    #pragma unroll
    for (int i = tid; i < 64 * 64; i += 256) {
        int r = i >> 6, c = i & 63;
        sQ[r][c] = Q[(size_t)(qrow0 + r) * ED + coff + c] * scale;
    }

    float m[4], l[4], o[4][4];
    #pragma unroll
    for (int i = 0; i < 4; i++) {
        m[i] = -1e30f; l[i] = 0.f;
        #pragma unroll
        for (int j = 0; j < 4; j++) o[i][j] = 0.f;
    }

    for (int kt = 0; kt < SEQ / 64; kt++) {
        const int krow0 = b * SEQ + kt * 64;
        __syncthreads();   // prev-iter PV reads done (also covers sQ visibility)

        #pragma unroll
        for (int i = tid; i < 64 * 64; i += 256) {
            int r = i >> 6, c = i & 63;
            sKP[r][SW(r, c)] = K[(size_t)(krow0 + r) * ED + coff + c];
            sV [r][SW(r, c)] = V[(size_t)(krow0 + r) * ED + coff + c];
        }
        __syncthreads();

        // S = (Q*scale) @ K^T   -> s[4][4] per thread (rows ty*4+i, cols tx*4+j)
        float s[4][4] = {};
        #pragma unroll 8
        for (int d = 0; d < 64; d++) {
            float ra[4], rb[4];
            #pragma unroll
            for (int i = 0; i < 4; i++) ra[i] = sQ[ty * 4 + i][d];
            #pragma unroll
            for (int j = 0; j < 4; j++) {
                int kr = tx * 4 + j;
                rb[j] = sKP[kr][SW(kr, d)];
            }
            #pragma unroll
            for (int i = 0; i < 4; i++)
                #pragma unroll
                for (int j = 0; j < 4; j++)
                    s[i][j] += ra[i] * rb[j];
        }

        // Online softmax. Row stats reduce across the 16 tx lanes (xor<16 stays
        // inside each half-warp; halves carry independent ty rows).
        #pragma unroll
        for (int i = 0; i < 4; i++) {
            float mx = s[i][0];
            #pragma unroll
            for (int j = 1; j < 4; j++) mx = fmaxf(mx, s[i][j]);
            #pragma unroll
            for (int off = 8; off >= 1; off >>= 1)
                mx = fmaxf(mx, __shfl_xor_sync(0xffffffffu, mx, off));
            float mn   = fmaxf(m[i], mx);
            float corr = __expf(m[i] - mn);
            m[i] = mn;
            float rs = 0.f;
            #pragma unroll
            for (int j = 0; j < 4; j++) {
                s[i][j] = __expf(s[i][j] - mn);
                rs += s[i][j];
            }
            #pragma unroll
            for (int off = 8; off >= 1; off >>= 1)
                rs += __shfl_xor_sync(0xffffffffu, rs, off);
            l[i] = l[i] * corr + rs;
            #pragma unroll
            for (int j = 0; j < 4; j++) o[i][j] *= corr;
        }

        __syncthreads();   // everyone done reading K from sKP
        #pragma unroll
        for (int i = 0; i < 4; i++)
            #pragma unroll
            for (int j = 0; j < 4; j++)
                sKP[ty * 4 + i][tx * 4 + j] = s[i][j];   // P, plain [q][k]
        __syncthreads();

        // O += P @ V
        #pragma unroll 8
        for (int k = 0; k < 64; k++) {
            float rp[4], rv[4];
            #pragma unroll
            for (int i = 0; i < 4; i++) rp[i] = sKP[ty * 4 + i][k];
            #pragma unroll
            for (int j = 0; j < 4; j++) rv[j] = sV[k][SW(k, tx * 4 + j)];
            #pragma unroll
            for (int i = 0; i < 4; i++)
                #pragma unroll
                for (int j = 0; j < 4; j++)
                    o[i][j] += rp[i] * rv[j];
        }
    }

    #pragma unroll
    for (int i = 0; i < 4; i++) {
        float inv = 1.0f / l[i];
        int r = qrow0 + ty * 4 + i;
        #pragma unroll
        for (int j = 0; j < 4; j++)
            ctx[(size_t)r * ED + coff + tx * 4 + j] = o[i][j] * inv;
    }
}

// ---------------------------------------------------------------------------
extern "C" void kernel_launch(void* const* d_in, const int* in_sizes, int n_in,
                              void* d_out, int out_size)
{
    const float* x  = (const float*)d_in[0];
    const float* wq = (const float*)d_in[1];
    const float* bq = (const float*)d_in[2];
    const float* wk = (const float*)d_in[3];
    const float* bk = (const float*)d_in[4];
    const float* wv = (const float*)d_in[5];
    const float* bv = (const float*)d_in[6];
    const float* wo = (const float*)d_in[7];
    const float* bo = (const float*)d_in[8];
    float* out = (float*)d_out;

    float *Qp, *Kp, *Vp, *Cp;
    cudaGetSymbolAddress((void**)&Qp, g_Q);
    cudaGetSymbolAddress((void**)&Kp, g_K);
    cudaGetSymbolAddress((void**)&Vp, g_V);
    cudaGetSymbolAddress((void**)&Cp, g_C);

    dim3 ggrid(ED / 64, MTOT / 64);   // (16, 64)

    gemm_bias<false><<<ggrid, 256>>>(x, nullptr, wq, bq, Qp, MTOT, ED, ED);
    gemm_bias<false><<<ggrid, 256>>>(x, nullptr, wk, bk, Kp, MTOT, ED, ED);
    gemm_bias<false><<<ggrid, 256>>>(x, nullptr, wv, bv, Vp, MTOT, ED, ED);

    attn_kernel<<<dim3(SEQ / 64, NH, BATCH), 256>>>(Qp, Kp, Vp, Cp);

    // out = (context + x) @ w_o + b_o   (residual fused into A-load)
    gemm_bias<true><<<ggrid, 256>>>(Cp, x, wo, bo, out, MTOT, ED, ED);
}

// round 2
// speedup vs baseline: 1.8466x; 1.8466x over previous
#include <cuda_runtime.h>
#include <stdint.h>

#define ED   1024
#define NH   16
#define HD   64
#define SEQ  2048
#define BATCH 2
#define MTOT (BATCH*SEQ)

// Scratch (allocation-free rule: __device__ globals)
__device__ float g_Q[MTOT * ED];
__device__ float g_K[MTOT * ED];
__device__ float g_V[MTOT * ED];
__device__ float g_C[MTOT * ED];

// ---------------------------------------------------------------------------
// tf32 helpers
// ---------------------------------------------------------------------------
__device__ __forceinline__ uint32_t f2tf(float x) {
    uint32_t r;
    asm("cvt.rna.tf32.f32 %0, %1;" : "=r"(r) : "f"(x));
    return r;
}
// a = hi + lo, both representable in tf32 (hi/lo as fp32 bit patterns w/ low 13 bits zero)
__device__ __forceinline__ void split_tf32(float x, uint32_t& h, uint32_t& l) {
    h = f2tf(x);
    float lf = x - __uint_as_float(h);
    l = f2tf(lf);
}
__device__ __forceinline__ void mma8(float* d, const uint32_t* a, uint32_t b0, uint32_t b1) {
    asm volatile(
        "mma.sync.aligned.m16n8k8.row.col.f32.tf32.tf32.f32 "
        "{%0,%1,%2,%3}, {%4,%5,%6,%7}, {%8,%9}, {%0,%1,%2,%3};\n"
        : "+f"(d[0]), "+f"(d[1]), "+f"(d[2]), "+f"(d[3])
        : "r"(a[0]), "r"(a[1]), "r"(a[2]), "r"(a[3]), "r"(b0), "r"(b1));
}
// 3xTF32: d += a*b with error compensation (drops only al*bl ~ 2^-22)
__device__ __forceinline__ void mma3(float* d, const uint32_t* ah, const uint32_t* al,
                                     uint32_t bh0, uint32_t bh1, uint32_t bl0, uint32_t bl1) {
    mma8(d, ah, bh0, bh1);
    mma8(d, al, bh0, bh1);
    mma8(d, ah, bl0, bl1);
}

// ---------------------------------------------------------------------------
// GEMM: C[4096,1024] = (A (+A2)) @ W[1024,1024] + bias, tensor cores, 3xTF32.
// 128x128 tile, BK=32, 256 threads (8 warps, 2x4), warp tile 64x32.
// Pads chosen so every quad fragment-LDS hits 32 distinct banks.
// ---------------------------------------------------------------------------
#define PA 36
#define PB 136

template <bool ADD>
__global__ void __launch_bounds__(256)
gemm_tc(const float* __restrict__ A, const float* __restrict__ A2,
        const float* __restrict__ W, const float* __restrict__ bias,
        float* __restrict__ C)
{
    __shared__ float sA[128 * PA];
    __shared__ float sB[32 * PB];

    const int tid  = threadIdx.x;
    const int w    = tid >> 5, lane = tid & 31, g = lane >> 2, t = lane & 3;
    const int wm   = w >> 2, wn = w & 3;
    const int m0   = blockIdx.y * 128, n0 = blockIdx.x * 128;

    float acc[4][4][4] = {};

    for (int k0 = 0; k0 < ED; k0 += 32) {
        __syncthreads();
        #pragma unroll
        for (int i = 0; i < 4; i++) {
            int id = tid + i * 256;
            int r = id >> 3, c4 = (id & 7) << 2;
            float4 v = *(const float4*)(A + (size_t)(m0 + r) * ED + k0 + c4);
            if (ADD) {
                float4 u = *(const float4*)(A2 + (size_t)(m0 + r) * ED + k0 + c4);
                v.x += u.x; v.y += u.y; v.z += u.z; v.w += u.w;
            }
            *(float4*)(sA + r * PA + c4) = v;
        }
        #pragma unroll
        for (int i = 0; i < 4; i++) {
            int id = tid + i * 256;
            int r = id >> 5, c4 = (id & 31) << 2;
            *(float4*)(sB + r * PB + c4) =
                *(const float4*)(W + (size_t)(k0 + r) * ED + n0 + c4);
        }
        __syncthreads();

        #pragma unroll
        for (int kc = 0; kc < 4; kc++) {
            uint32_t ah[4][4], al[4][4];
            #pragma unroll
            for (int mt = 0; mt < 4; mt++) {
                int row = wm * 64 + mt * 16;
                split_tf32(sA[(row + g    ) * PA + kc * 8 + t    ], ah[mt][0], al[mt][0]);
                split_tf32(sA[(row + g + 8) * PA + kc * 8 + t    ], ah[mt][1], al[mt][1]);
                split_tf32(sA[(row + g    ) * PA + kc * 8 + t + 4], ah[mt][2], al[mt][2]);
                split_tf32(sA[(row + g + 8) * PA + kc * 8 + t + 4], ah[mt][3], al[mt][3]);
            }
            uint32_t bh[4][2], bl[4][2];
            #pragma unroll
            for (int nc = 0; nc < 4; nc++) {
                int col = wn * 32 + nc * 8 + g;
                split_tf32(sB[(kc * 8 + t    ) * PB + col], bh[nc][0], bl[nc][0]);
                split_tf32(sB[(kc * 8 + t + 4) * PB + col], bh[nc][1], bl[nc][1]);
            }
            #pragma unroll
            for (int mt = 0; mt < 4; mt++)
                #pragma unroll
                for (int nc = 0; nc < 4; nc++)
                    mma3(acc[mt][nc], ah[mt], al[mt],
                         bh[nc][0], bh[nc][1], bl[nc][0], bl[nc][1]);
        }
    }

    #pragma unroll
    for (int mt = 0; mt < 4; mt++) {
        int row = m0 + wm * 64 + mt * 16 + g;
        #pragma unroll
        for (int nc = 0; nc < 4; nc++) {
            int col = n0 + wn * 32 + nc * 8 + 2 * t;
            float b0v = bias[col], b1v = bias[col + 1];
            C[(size_t)row * ED + col]           = acc[mt][nc][0] + b0v;
            C[(size_t)row * ED + col + 1]       = acc[mt][nc][1] + b1v;
            C[(size_t)(row + 8) * ED + col]     = acc[mt][nc][2] + b0v;
            C[(size_t)(row + 8) * ED + col + 1] = acc[mt][nc][3] + b1v;
        }
    }
}

// ---------------------------------------------------------------------------
// Flash attention on tensor cores (3xTF32). CTA = 128 threads (4 warps),
// one 64-q tile per (head,batch). Warp w owns q rows 16w..16w+15.
// sKP holds K during S, recycled to hold P for P@V. sV padded for B-frags.
// ---------------------------------------------------------------------------
#define PK 68
#define PV 72

__global__ void __launch_bounds__(128)
attn_tc(const float* __restrict__ Q, const float* __restrict__ K,
        const float* __restrict__ V, float* __restrict__ ctx)
{
    __shared__ float sKP[64 * PK];
    __shared__ float sV [64 * PV];

    const int tid = threadIdx.x;
    const int w = tid >> 5, lane = tid & 31, g = lane >> 2, t = lane & 3;
    const int qt = blockIdx.x, h = blockIdx.y, b = blockIdx.z;
    const int qrow0 = b * SEQ + qt * 64;
    const int coff  = h * HD;

    // Stage Q (pre-scaled by 1/sqrt(64)) through sKP, split into register frags.
    #pragma unroll
    for (int i = 0; i < 8; i++) {
        int id = tid + i * 128;
        int r = id >> 4, c4 = (id & 15) << 2;
        float4 v = *(const float4*)(Q + (size_t)(qrow0 + r) * ED + coff + c4);
        v.x *= 0.125f; v.y *= 0.125f; v.z *= 0.125f; v.w *= 0.125f;
        *(float4*)(sKP + r * PK + c4) = v;
    }
    __syncthreads();

    uint32_t qh[8][4], ql[8][4];
    #pragma unroll
    for (int kc = 0; kc < 8; kc++) {
        int row = w * 16;
        split_tf32(sKP[(row + g    ) * PK + kc * 8 + t    ], qh[kc][0], ql[kc][0]);
        split_tf32(sKP[(row + g + 8) * PK + kc * 8 + t    ], qh[kc][1], ql[kc][1]);
        split_tf32(sKP[(row + g    ) * PK + kc * 8 + t + 4], qh[kc][2], ql[kc][2]);
        split_tf32(sKP[(row + g + 8) * PK + kc * 8 + t + 4], qh[kc][3], ql[kc][3]);
    }

    float m1 = -1e30f, m2 = -1e30f, l1 = 0.f, l2 = 0.f;
    float o[8][4] = {};

    for (int kt = 0; kt < SEQ / 64; kt++) {
        __syncthreads();   // prior-iter reads of sKP/sV complete (covers Q frag loads too)
        const int krow0 = b * SEQ + kt * 64;
        #pragma unroll
        for (int i = 0; i < 8; i++) {
            int id = tid + i * 128;
            int r = id >> 4, c4 = (id & 15) << 2;
            *(float4*)(sKP + r * PK + c4) =
                *(const float4*)(K + (size_t)(krow0 + r) * ED + coff + c4);
            *(float4*)(sV + r * PV + c4) =
                *(const float4*)(V + (size_t)(krow0 + r) * ED + coff + c4);
        }
        __syncthreads();

        // S = Q @ K^T  (m=16q, n=64kv, k=64d per warp)
        float s[8][4] = {};
        #pragma unroll
        for (int kc = 0; kc < 8; kc++) {
            #pragma unroll
            for (int nc = 0; nc < 8; nc++) {
                uint32_t bh0, bl0, bh1, bl1;
                split_tf32(sKP[(nc * 8 + g) * PK + kc * 8 + t    ], bh0, bl0);
                split_tf32(sKP[(nc * 8 + g) * PK + kc * 8 + t + 4], bh1, bl1);
                mma3(s[nc], qh[kc], ql[kc], bh0, bh1, bl0, bl1);
            }
        }

        // Online softmax: rows r1=g, r2=g+8; reduce across the 4-lane quad.
        float tm1 = -1e30f, tm2 = -1e30f;
        #pragma unroll
        for (int nc = 0; nc < 8; nc++) {
            tm1 = fmaxf(tm1, fmaxf(s[nc][0], s[nc][1]));
            tm2 = fmaxf(tm2, fmaxf(s[nc][2], s[nc][3]));
        }
        tm1 = fmaxf(tm1, __shfl_xor_sync(0xffffffffu, tm1, 1));
        tm1 = fmaxf(tm1, __shfl_xor_sync(0xffffffffu, tm1, 2));
        tm2 = fmaxf(tm2, __shfl_xor_sync(0xffffffffu, tm2, 1));
        tm2 = fmaxf(tm2, __shfl_xor_sync(0xffffffffu, tm2, 2));

        float mn1 = fmaxf(m1, tm1), mn2 = fmaxf(m2, tm2);
        float c1 = __expf(m1 - mn1), c2 = __expf(m2 - mn2);
        m1 = mn1; m2 = mn2;

        float rs1 = 0.f, rs2 = 0.f;
        #pragma unroll
        for (int nc = 0; nc < 8; nc++) {
            s[nc][0] = __expf(s[nc][0] - mn1);
            s[nc][1] = __expf(s[nc][1] - mn1);
            s[nc][2] = __expf(s[nc][2] - mn2);
            s[nc][3] = __expf(s[nc][3] - mn2);
            rs1 += s[nc][0] + s[nc][1];
            rs2 += s[nc][2] + s[nc][3];
        }
        rs1 += __shfl_xor_sync(0xffffffffu, rs1, 1);
        rs1 += __shfl_xor_sync(0xffffffffu, rs1, 2);
        rs2 += __shfl_xor_sync(0xffffffffu, rs2, 1);
        rs2 += __shfl_xor_sync(0xffffffffu, rs2, 2);
        l1 = l1 * c1 + rs1;
        l2 = l2 * c2 + rs2;
        #pragma unroll
        for (int nc = 0; nc < 8; nc++) {
            o[nc][0] *= c1; o[nc][1] *= c1;
            o[nc][2] *= c2; o[nc][3] *= c2;
        }

        __syncthreads();   // ALL warps finished reading K from sKP
        // Write P into sKP (each warp writes & later reads only its own 16 rows)
        #pragma unroll
        for (int nc = 0; nc < 8; nc++) {
            int row = w * 16 + g;
            *(float2*)(sKP + row * PK + nc * 8 + 2 * t)       = make_float2(s[nc][0], s[nc][1]);
            *(float2*)(sKP + (row + 8) * PK + nc * 8 + 2 * t) = make_float2(s[nc][2], s[nc][3]);
        }
        __syncwarp();

        // O += P @ V   (m=16q, n=64d, k=64kv)
        #pragma unroll
        for (int kc = 0; kc < 8; kc++) {
            uint32_t ahh[4], all[4];
            int row = w * 16;
            split_tf32(sKP[(row + g    ) * PK + kc * 8 + t    ], ahh[0], all[0]);
            split_tf32(sKP[(row + g + 8) * PK + kc * 8 + t    ], ahh[1], all[1]);
            split_tf32(sKP[(row + g    ) * PK + kc * 8 + t + 4], ahh[2], all[2]);
            split_tf32(sKP[(row + g + 8) * PK + kc * 8 + t + 4], ahh[3], all[3]);
            #pragma unroll
            for (int nc = 0; nc < 8; nc++) {
                uint32_t bh0, bl0, bh1, bl1;
                split_tf32(sV[(kc * 8 + t    ) * PV + nc * 8 + g], bh0, bl0);
                split_tf32(sV[(kc * 8 + t + 4) * PV + nc * 8 + g], bh1, bl1);
                mma3(o[nc], ahh, all, bh0, bh1, bl0, bl1);
            }
        }
    }

    const float i1 = 1.f / l1, i2 = 1.f / l2;
    #pragma unroll
    for (int nc = 0; nc < 8; nc++) {
        int row = qrow0 + w * 16 + g;
        int col = coff + nc * 8 + 2 * t;
        ctx[(size_t)row * ED + col]           = o[nc][0] * i1;
        ctx[(size_t)row * ED + col + 1]       = o[nc][1] * i1;
        ctx[(size_t)(row + 8) * ED + col]     = o[nc][2] * i2;
        ctx[(size_t)(row + 8) * ED + col + 1] = o[nc][3] * i2;
    }
}

// ---------------------------------------------------------------------------
extern "C" void kernel_launch(void* const* d_in, const int* in_sizes, int n_in,
                              void* d_out, int out_size)
{
    const float* x  = (const float*)d_in[0];
    const float* wq = (const float*)d_in[1];
    const float* bq = (const float*)d_in[2];
    const float* wk = (const float*)d_in[3];
    const float* bk = (const float*)d_in[4];
    const float* wv = (const float*)d_in[5];
    const float* bv = (const float*)d_in[6];
    const float* wo = (const float*)d_in[7];
    const float* bo = (const float*)d_in[8];
    float* out = (float*)d_out;

    float *Qp, *Kp, *Vp, *Cp;
    cudaGetSymbolAddress((void**)&Qp, g_Q);
    cudaGetSymbolAddress((void**)&Kp, g_K);
    cudaGetSymbolAddress((void**)&Vp, g_V);
    cudaGetSymbolAddress((void**)&Cp, g_C);

    dim3 ggrid(ED / 128, MTOT / 128);   // (8, 32)

    gemm_tc<false><<<ggrid, 256>>>(x, nullptr, wq, bq, Qp);
    gemm_tc<false><<<ggrid, 256>>>(x, nullptr, wk, bk, Kp);
    gemm_tc<false><<<ggrid, 256>>>(x, nullptr, wv, bv, Vp);

    attn_tc<<<dim3(SEQ / 64, NH, BATCH), 128>>>(Qp, Kp, Vp, Cp);

    // out = (context + x) @ w_o + b_o   (residual fused into A-load)
    gemm_tc<true><<<ggrid, 256>>>(Cp, x, wo, bo, out);
}

// round 3
// speedup vs baseline: 2.0059x; 1.0863x over previous
#include <cuda_runtime.h>
#include <stdint.h>

#define ED   1024
#define NH   16
#define HD   64
#define SEQ  2048
#define BATCH 2
#define MTOT (BATCH*SEQ)

__device__ float g_Q[MTOT * ED];
__device__ float g_K[MTOT * ED];
__device__ float g_V[MTOT * ED];
__device__ float g_C[MTOT * ED];

// ---------------------------------------------------------------------------
// tf32 helpers
// ---------------------------------------------------------------------------
__device__ __forceinline__ uint32_t f2tf(float x) {
    uint32_t r;
    asm("cvt.rna.tf32.f32 %0, %1;" : "=r"(r) : "f"(x));
    return r;
}
__device__ __forceinline__ void split_tf32(float x, uint32_t& h, uint32_t& l) {
    h = f2tf(x);
    l = f2tf(x - __uint_as_float(h));
}
__device__ __forceinline__ void mma8(float* d, const uint32_t* a, uint32_t b0, uint32_t b1) {
    asm volatile(
        "mma.sync.aligned.m16n8k8.row.col.f32.tf32.tf32.f32 "
        "{%0,%1,%2,%3}, {%4,%5,%6,%7}, {%8,%9}, {%0,%1,%2,%3};\n"
        : "+f"(d[0]), "+f"(d[1]), "+f"(d[2]), "+f"(d[3])
        : "r"(a[0]), "r"(a[1]), "r"(a[2]), "r"(a[3]), "r"(b0), "r"(b1));
}

// ---------------------------------------------------------------------------
// GEMM: C[4096,1024] = (A (+A2)) @ W + bias. 3xTF32 (full accuracy).
// 128x128 tile, BK=16, 256 threads (8 warps 2x4), warp tile 64x32.
// hi/lo pre-split in smem at staging; register prefetch pipeline.
// Pads: PA=20 -> frag bank (4g+t) distinct; PB=136 -> (8t+g) distinct.
// ---------------------------------------------------------------------------
#define PA 20
#define PB 136

template <bool ADD>
__global__ void __launch_bounds__(256)
gemm_tc(const float* __restrict__ A, const float* __restrict__ A2,
        const float* __restrict__ W, const float* __restrict__ bias,
        float* __restrict__ C)
{
    __shared__ float sAh[128 * PA], sAl[128 * PA];
    __shared__ float sBh[16 * PB],  sBl[16 * PB];

    const int tid = threadIdx.x;
    const int w = tid >> 5, lane = tid & 31, g = lane >> 2, t = lane & 3;
    const int wm = w >> 2, wn = w & 3;
    const int m0 = blockIdx.y * 128, n0 = blockIdx.x * 128;

    // staging coords
    const int ar = tid >> 2,            ac = (tid & 3) << 2;        // A row/col (+r2 for 2nd)
    const int br = tid >> 5,            bc = (tid & 31) << 2;       // B row/col

    float acc[4][4][4] = {};
    float4 pa0, pa1, pb0, pb1;

    // prefetch k0 = 0
    {
        pa0 = *(const float4*)(A + (size_t)(m0 + ar) * ED + ac);
        pa1 = *(const float4*)(A + (size_t)(m0 + ar + 64) * ED + ac);
        if (ADD) {
            float4 u0 = *(const float4*)(A2 + (size_t)(m0 + ar) * ED + ac);
            float4 u1 = *(const float4*)(A2 + (size_t)(m0 + ar + 64) * ED + ac);
            pa0.x += u0.x; pa0.y += u0.y; pa0.z += u0.z; pa0.w += u0.w;
            pa1.x += u1.x; pa1.y += u1.y; pa1.z += u1.z; pa1.w += u1.w;
        }
        pb0 = *(const float4*)(W + (size_t)br * ED + n0 + bc);
        pb1 = *(const float4*)(W + (size_t)(br + 8) * ED + n0 + bc);
    }

    for (int k0 = 0; k0 < ED; k0 += 16) {
        __syncthreads();   // previous compute done reading smem
        // store prefetched tile with split
        {
            const float* v;
            uint32_t h, l;
            v = &pa0.x;
            #pragma unroll
            for (int j = 0; j < 4; j++) {
                split_tf32(v[j], h, l);
                sAh[ar * PA + ac + j] = __uint_as_float(h);
                sAl[ar * PA + ac + j] = __uint_as_float(l);
            }
            v = &pa1.x;
            #pragma unroll
            for (int j = 0; j < 4; j++) {
                split_tf32(v[j], h, l);
                sAh[(ar + 64) * PA + ac + j] = __uint_as_float(h);
                sAl[(ar + 64) * PA + ac + j] = __uint_as_float(l);
            }
            v = &pb0.x;
            #pragma unroll
            for (int j = 0; j < 4; j++) {
                split_tf32(v[j], h, l);
                sBh[br * PB + bc + j] = __uint_as_float(h);
                sBl[br * PB + bc + j] = __uint_as_float(l);
            }
            v = &pb1.x;
            #pragma unroll
            for (int j = 0; j < 4; j++) {
                split_tf32(v[j], h, l);
                sBh[(br + 8) * PB + bc + j] = __uint_as_float(h);
                sBl[(br + 8) * PB + bc + j] = __uint_as_float(l);
            }
        }
        __syncthreads();

        // prefetch next tile (overlaps with compute below)
        if (k0 + 16 < ED) {
            int kn = k0 + 16;
            pa0 = *(const float4*)(A + (size_t)(m0 + ar) * ED + kn + ac);
            pa1 = *(const float4*)(A + (size_t)(m0 + ar + 64) * ED + kn + ac);
            if (ADD) {
                float4 u0 = *(const float4*)(A2 + (size_t)(m0 + ar) * ED + kn + ac);
                float4 u1 = *(const float4*)(A2 + (size_t)(m0 + ar + 64) * ED + kn + ac);
                pa0.x += u0.x; pa0.y += u0.y; pa0.z += u0.z; pa0.w += u0.w;
                pa1.x += u1.x; pa1.y += u1.y; pa1.z += u1.z; pa1.w += u1.w;
            }
            pb0 = *(const float4*)(W + (size_t)(kn + br) * ED + n0 + bc);
            pb1 = *(const float4*)(W + (size_t)(kn + br + 8) * ED + n0 + bc);
        }

        #pragma unroll
        for (int kc = 0; kc < 2; kc++) {
            uint32_t ah[4][4], al[4][4];
            #pragma unroll
            for (int mt = 0; mt < 4; mt++) {
                int row = wm * 64 + mt * 16;
                ah[mt][0] = __float_as_uint(sAh[(row + g    ) * PA + kc * 8 + t    ]);
                ah[mt][1] = __float_as_uint(sAh[(row + g + 8) * PA + kc * 8 + t    ]);
                ah[mt][2] = __float_as_uint(sAh[(row + g    ) * PA + kc * 8 + t + 4]);
                ah[mt][3] = __float_as_uint(sAh[(row + g + 8) * PA + kc * 8 + t + 4]);
                al[mt][0] = __float_as_uint(sAl[(row + g    ) * PA + kc * 8 + t    ]);
                al[mt][1] = __float_as_uint(sAl[(row + g + 8) * PA + kc * 8 + t    ]);
                al[mt][2] = __float_as_uint(sAl[(row + g    ) * PA + kc * 8 + t + 4]);
                al[mt][3] = __float_as_uint(sAl[(row + g + 8) * PA + kc * 8 + t + 4]);
            }
            uint32_t bh[4][2], bl[4][2];
            #pragma unroll
            for (int nc = 0; nc < 4; nc++) {
                int col = wn * 32 + nc * 8 + g;
                bh[nc][0] = __float_as_uint(sBh[(kc * 8 + t    ) * PB + col]);
                bh[nc][1] = __float_as_uint(sBh[(kc * 8 + t + 4) * PB + col]);
                bl[nc][0] = __float_as_uint(sBl[(kc * 8 + t    ) * PB + col]);
                bl[nc][1] = __float_as_uint(sBl[(kc * 8 + t + 4) * PB + col]);
            }
            #pragma unroll
            for (int mt = 0; mt < 4; mt++)
                #pragma unroll
                for (int nc = 0; nc < 4; nc++) {
                    mma8(acc[mt][nc], ah[mt], bh[nc][0], bh[nc][1]);
                    mma8(acc[mt][nc], al[mt], bh[nc][0], bh[nc][1]);
                    mma8(acc[mt][nc], ah[mt], bl[nc][0], bl[nc][1]);
                }
        }
    }

    #pragma unroll
    for (int mt = 0; mt < 4; mt++) {
        int row = m0 + wm * 64 + mt * 16 + g;
        #pragma unroll
        for (int nc = 0; nc < 4; nc++) {
            int col = n0 + wn * 32 + nc * 8 + 2 * t;
            float b0v = bias[col], b1v = bias[col + 1];
            C[(size_t)row * ED + col]           = acc[mt][nc][0] + b0v;
            C[(size_t)row * ED + col + 1]       = acc[mt][nc][1] + b1v;
            C[(size_t)(row + 8) * ED + col]     = acc[mt][nc][2] + b0v;
            C[(size_t)(row + 8) * ED + col + 1] = acc[mt][nc][3] + b1v;
        }
    }
}

// ---------------------------------------------------------------------------
// Flash attention, tensor cores. Q split (regs, exact); K/V/P tf32-rounded
// once at staging (error-budgeted: ~2e-4/stage, 3 stages).
// S = 2 mma per pair, PV = 1 mma per pair.
// PK=68 -> K/P frag bank (4g+t) distinct; PV=72 -> V frag bank (8t+g) distinct.
// ---------------------------------------------------------------------------
#define PK 68
#define PVP 72

__global__ void __launch_bounds__(128)
attn_tc(const float* __restrict__ Q, const float* __restrict__ K,
        const float* __restrict__ V, float* __restrict__ ctx)
{
    __shared__ float sKP[64 * PK];   // K-hi during S; P-hi during PV
    __shared__ float sV [64 * PVP];  // V-hi

    const int tid = threadIdx.x;
    const int w = tid >> 5, lane = tid & 31, g = lane >> 2, t = lane & 3;
    const int qt = blockIdx.x, h = blockIdx.y, b = blockIdx.z;
    const int qrow0 = b * SEQ + qt * 64;
    const int coff  = h * HD;

    // Stage Q (pre-scaled) through sKP, split into register frags (exact).
    #pragma unroll
    for (int i = 0; i < 8; i++) {
        int id = tid + i * 128;
        int r = id >> 4, c4 = (id & 15) << 2;
        float4 v = *(const float4*)(Q + (size_t)(qrow0 + r) * ED + coff + c4);
        v.x *= 0.125f; v.y *= 0.125f; v.z *= 0.125f; v.w *= 0.125f;
        *(float4*)(sKP + r * PK + c4) = v;
    }
    __syncthreads();

    uint32_t qh[8][4], ql[8][4];
    #pragma unroll
    for (int kc = 0; kc < 8; kc++) {
        int row = w * 16;
        split_tf32(sKP[(row + g    ) * PK + kc * 8 + t    ], qh[kc][0], ql[kc][0]);
        split_tf32(sKP[(row + g + 8) * PK + kc * 8 + t    ], qh[kc][1], ql[kc][1]);
        split_tf32(sKP[(row + g    ) * PK + kc * 8 + t + 4], qh[kc][2], ql[kc][2]);
        split_tf32(sKP[(row + g + 8) * PK + kc * 8 + t + 4], qh[kc][3], ql[kc][3]);
    }

    float m1 = -1e30f, m2 = -1e30f, l1 = 0.f, l2 = 0.f;
    float o[8][4] = {};

    for (int kt = 0; kt < SEQ / 64; kt++) {
        __syncthreads();   // prior-iter P/V reads done (covers Q frag loads too)
        const int krow0 = b * SEQ + kt * 64;
        #pragma unroll
        for (int i = 0; i < 8; i++) {
            int id = tid + i * 128;
            int r = id >> 4, c4 = (id & 15) << 2;
            float4 kv = *(const float4*)(K + (size_t)(krow0 + r) * ED + coff + c4);
            float4 vv = *(const float4*)(V + (size_t)(krow0 + r) * ED + coff + c4);
            sKP[r * PK + c4    ] = __uint_as_float(f2tf(kv.x));
            sKP[r * PK + c4 + 1] = __uint_as_float(f2tf(kv.y));
            sKP[r * PK + c4 + 2] = __uint_as_float(f2tf(kv.z));
            sKP[r * PK + c4 + 3] = __uint_as_float(f2tf(kv.w));
            sV [r * PVP + c4    ] = __uint_as_float(f2tf(vv.x));
            sV [r * PVP + c4 + 1] = __uint_as_float(f2tf(vv.y));
            sV [r * PVP + c4 + 2] = __uint_as_float(f2tf(vv.z));
            sV [r * PVP + c4 + 3] = __uint_as_float(f2tf(vv.w));
        }
        __syncthreads();

        // S = Q @ K^T   (2 mma: qh*kh + ql*kh)
        float s[8][4] = {};
        #pragma unroll
        for (int kc = 0; kc < 8; kc++) {
            #pragma unroll
            for (int nc = 0; nc < 8; nc++) {
                uint32_t bh0 = __float_as_uint(sKP[(nc * 8 + g) * PK + kc * 8 + t    ]);
                uint32_t bh1 = __float_as_uint(sKP[(nc * 8 + g) * PK + kc * 8 + t + 4]);
                mma8(s[nc], qh[kc], bh0, bh1);
                mma8(s[nc], ql[kc], bh0, bh1);
            }
        }

        // Online softmax (rows g, g+8; quad reduction)
        float tm1 = -1e30f, tm2 = -1e30f;
        #pragma unroll
        for (int nc = 0; nc < 8; nc++) {
            tm1 = fmaxf(tm1, fmaxf(s[nc][0], s[nc][1]));
            tm2 = fmaxf(tm2, fmaxf(s[nc][2], s[nc][3]));
        }
        tm1 = fmaxf(tm1, __shfl_xor_sync(0xffffffffu, tm1, 1));
        tm1 = fmaxf(tm1, __shfl_xor_sync(0xffffffffu, tm1, 2));
        tm2 = fmaxf(tm2, __shfl_xor_sync(0xffffffffu, tm2, 1));
        tm2 = fmaxf(tm2, __shfl_xor_sync(0xffffffffu, tm2, 2));

        float mn1 = fmaxf(m1, tm1), mn2 = fmaxf(m2, tm2);
        float c1 = __expf(m1 - mn1), c2 = __expf(m2 - mn2);
        m1 = mn1; m2 = mn2;

        float rs1 = 0.f, rs2 = 0.f;
        #pragma unroll
        for (int nc = 0; nc < 8; nc++) {
            s[nc][0] = __expf(s[nc][0] - mn1);
            s[nc][1] = __expf(s[nc][1] - mn1);
            s[nc][2] = __expf(s[nc][2] - mn2);
            s[nc][3] = __expf(s[nc][3] - mn2);
            rs1 += s[nc][0] + s[nc][1];
            rs2 += s[nc][2] + s[nc][3];
        }
        rs1 += __shfl_xor_sync(0xffffffffu, rs1, 1);
        rs1 += __shfl_xor_sync(0xffffffffu, rs1, 2);
        rs2 += __shfl_xor_sync(0xffffffffu, rs2, 1);
        rs2 += __shfl_xor_sync(0xffffffffu, rs2, 2);
        l1 = l1 * c1 + rs1;
        l2 = l2 * c2 + rs2;
        #pragma unroll
        for (int nc = 0; nc < 8; nc++) {
            o[nc][0] *= c1; o[nc][1] *= c1;
            o[nc][2] *= c2; o[nc][3] *= c2;
        }

        __syncthreads();   // all warps done reading K from sKP
        // Write P-hi (tf32-rounded) into sKP; each warp owns its 16 rows.
        #pragma unroll
        for (int nc = 0; nc < 8; nc++) {
            int row = w * 16 + g;
            float2 p01 = make_float2(__uint_as_float(f2tf(s[nc][0])),
                                     __uint_as_float(f2tf(s[nc][1])));
            float2 p23 = make_float2(__uint_as_float(f2tf(s[nc][2])),
                                     __uint_as_float(f2tf(s[nc][3])));
            *(float2*)(sKP + row * PK + nc * 8 + 2 * t)       = p01;
            *(float2*)(sKP + (row + 8) * PK + nc * 8 + 2 * t) = p23;
        }
        __syncwarp();

        // O += P @ V   (1 mma per pair)
        #pragma unroll
        for (int kc = 0; kc < 8; kc++) {
            uint32_t a[4];
            int row = w * 16;
            a[0] = __float_as_uint(sKP[(row + g    ) * PK + kc * 8 + t    ]);
            a[1] = __float_as_uint(sKP[(row + g + 8) * PK + kc * 8 + t    ]);
            a[2] = __float_as_uint(sKP[(row + g    ) * PK + kc * 8 + t + 4]);
            a[3] = __float_as_uint(sKP[(row + g + 8) * PK + kc * 8 + t + 4]);
            #pragma unroll
            for (int nc = 0; nc < 8; nc++) {
                uint32_t bh0 = __float_as_uint(sV[(kc * 8 + t    ) * PVP + nc * 8 + g]);
                uint32_t bh1 = __float_as_uint(sV[(kc * 8 + t + 4) * PVP + nc * 8 + g]);
                mma8(o[nc], a, bh0, bh1);
            }
        }
    }

    const float i1 = 1.f / l1, i2 = 1.f / l2;
    #pragma unroll
    for (int nc = 0; nc < 8; nc++) {
        int row = qrow0 + w * 16 + g;
        int col = coff + nc * 8 + 2 * t;
        ctx[(size_t)row * ED + col]           = o[nc][0] * i1;
        ctx[(size_t)row * ED + col + 1]       = o[nc][1] * i1;
        ctx[(size_t)(row + 8) * ED + col]     = o[nc][2] * i2;
        ctx[(size_t)(row + 8) * ED + col + 1] = o[nc][3] * i2;
    }
}

// ---------------------------------------------------------------------------
extern "C" void kernel_launch(void* const* d_in, const int* in_sizes, int n_in,
                              void* d_out, int out_size)
{
    const float* x  = (const float*)d_in[0];
    const float* wq = (const float*)d_in[1];
    const float* bq = (const float*)d_in[2];
    const float* wk = (const float*)d_in[3];
    const float* bk = (const float*)d_in[4];
    const float* wv = (const float*)d_in[5];
    const float* bv = (const float*)d_in[6];
    const float* wo = (const float*)d_in[7];
    const float* bo = (const float*)d_in[8];
    float* out = (float*)d_out;

    float *Qp, *Kp, *Vp, *Cp;
    cudaGetSymbolAddress((void**)&Qp, g_Q);
    cudaGetSymbolAddress((void**)&Kp, g_K);
    cudaGetSymbolAddress((void**)&Vp, g_V);
    cudaGetSymbolAddress((void**)&Cp, g_C);

    dim3 ggrid(ED / 128, MTOT / 128);   // (8, 32)

    gemm_tc<false><<<ggrid, 256>>>(x, nullptr, wq, bq, Qp);
    gemm_tc<false><<<ggrid, 256>>>(x, nullptr, wk, bk, Kp);
    gemm_tc<false><<<ggrid, 256>>>(x, nullptr, wv, bv, Vp);

    attn_tc<<<dim3(SEQ / 64, NH, BATCH), 128>>>(Qp, Kp, Vp, Cp);

    gemm_tc<true><<<ggrid, 256>>>(Cp, x, wo, bo, out);
}

// round 4
// speedup vs baseline: 3.7770x; 1.8829x over previous
#include <cuda_runtime.h>
#include <stdint.h>

#define ED   1024
#define NH   16
#define HD   64
#define SEQ  2048
#define BATCH 2
#define MTOT (BATCH*SEQ)

__device__ float g_Q[MTOT * ED];
__device__ float g_K[MTOT * ED];
__device__ float g_V[MTOT * ED];
__device__ float g_C[MTOT * ED];

// ---------------------------------------------------------------------------
// helpers
// ---------------------------------------------------------------------------
__device__ __forceinline__ uint32_t f2tf(float x) {          // RNE round to tf32
    uint32_t r;
    asm("cvt.rna.tf32.f32 %0, %1;" : "=r"(r) : "f"(x));
    return r;
}
__device__ __forceinline__ void mma8(float* d, const uint32_t* a, uint32_t b0, uint32_t b1) {
    asm volatile(
        "mma.sync.aligned.m16n8k8.row.col.f32.tf32.tf32.f32 "
        "{%0,%1,%2,%3}, {%4,%5,%6,%7}, {%8,%9}, {%0,%1,%2,%3};\n"
        : "+f"(d[0]), "+f"(d[1]), "+f"(d[2]), "+f"(d[3])
        : "r"(a[0]), "r"(a[1]), "r"(a[2]), "r"(a[3]), "r"(b0), "r"(b1));
}
__device__ __forceinline__ void cpa16(void* sdst, const void* gsrc) {
    uint32_t sa = (uint32_t)__cvta_generic_to_shared(sdst);
    asm volatile("cp.async.cg.shared.global [%0], [%1], 16;\n" :: "r"(sa), "l"(gsrc));
}
#define CP_COMMIT() asm volatile("cp.async.commit_group;\n" ::: "memory")
#define CP_WAIT1()  asm volatile("cp.async.wait_group 1;\n" ::: "memory")
#define CP_WAIT0()  asm volatile("cp.async.wait_group 0;\n" ::: "memory")

// exact split: x = hi + lo, hi = tf32-truncation (HW ignores low 13 bits)
__device__ __forceinline__ void split_mask(float x, uint32_t& h, uint32_t& l) {
    h = __float_as_uint(x) & 0xffffe000u;
    l = __float_as_uint(x - __uint_as_float(h));
}

// ---------------------------------------------------------------------------
// GEMM: C[4096,1024] = A @ W + bias.  2xTF32 (A exact-split, W RNE-rounded).
// 128x128 tile, BK=16, 256 threads (8 warps 2x4), warp tile 64x32.
// cp.async double-buffered. Pads: PA=20, PB=136 -> conflict-free frag LDS.
// ---------------------------------------------------------------------------
#define PA 20
#define PB 136

__global__ void __launch_bounds__(256)
gemm_tc(const float* __restrict__ A, const float* __restrict__ W,
        const float* __restrict__ bias, float* __restrict__ C)
{
    __shared__ float sA[2][128 * PA];
    __shared__ float sB[2][16 * PB];

    const int tid = threadIdx.x;
    const int w = tid >> 5, lane = tid & 31, g = lane >> 2, t = lane & 3;
    const int wm = w >> 2, wn = w & 3;
    const int m0 = blockIdx.y * 128, n0 = blockIdx.x * 128;

    float acc[4][4][4] = {};

    // stage k0=0
    {
        #pragma unroll
        for (int i = 0; i < 2; i++) {
            int id = tid + i * 256;
            int r = id >> 2, c4 = (id & 3) << 2;
            cpa16(&sA[0][r * PA + c4], A + (size_t)(m0 + r) * ED + c4);
        }
        #pragma unroll
        for (int i = 0; i < 2; i++) {
            int id = tid + i * 256;
            int r = id >> 5, c4 = (id & 31) << 2;
            cpa16(&sB[0][r * PB + c4], W + (size_t)r * ED + n0 + c4);
        }
        CP_COMMIT();
    }

    int buf = 0;
    for (int k0 = 0; k0 < ED; k0 += 16) {
        const bool more = (k0 + 16 < ED);
        if (more) {
            int kn = k0 + 16;
            #pragma unroll
            for (int i = 0; i < 2; i++) {
                int id = tid + i * 256;
                int r = id >> 2, c4 = (id & 3) << 2;
                cpa16(&sA[buf ^ 1][r * PA + c4], A + (size_t)(m0 + r) * ED + kn + c4);
            }
            #pragma unroll
            for (int i = 0; i < 2; i++) {
                int id = tid + i * 256;
                int r = id >> 5, c4 = (id & 31) << 2;
                cpa16(&sB[buf ^ 1][r * PB + c4], W + (size_t)(kn + r) * ED + n0 + c4);
            }
            CP_COMMIT();
            CP_WAIT1();
        } else {
            CP_WAIT0();
        }
        __syncthreads();

        const float* cA = sA[buf];
        const float* cB = sB[buf];
        #pragma unroll
        for (int kc = 0; kc < 2; kc++) {
            uint32_t ah[4][4], al[4][4];
            #pragma unroll
            for (int mt = 0; mt < 4; mt++) {
                int row = wm * 64 + mt * 16;
                split_mask(cA[(row + g    ) * PA + kc * 8 + t    ], ah[mt][0], al[mt][0]);
                split_mask(cA[(row + g + 8) * PA + kc * 8 + t    ], ah[mt][1], al[mt][1]);
                split_mask(cA[(row + g    ) * PA + kc * 8 + t + 4], ah[mt][2], al[mt][2]);
                split_mask(cA[(row + g + 8) * PA + kc * 8 + t + 4], ah[mt][3], al[mt][3]);
            }
            uint32_t bh[4][2];
            #pragma unroll
            for (int nc = 0; nc < 4; nc++) {
                int col = wn * 32 + nc * 8 + g;
                bh[nc][0] = f2tf(cB[(kc * 8 + t    ) * PB + col]);   // RNE (kills trunc bias)
                bh[nc][1] = f2tf(cB[(kc * 8 + t + 4) * PB + col]);
            }
            #pragma unroll
            for (int mt = 0; mt < 4; mt++)
                #pragma unroll
                for (int nc = 0; nc < 4; nc++) {
                    mma8(acc[mt][nc], ah[mt], bh[nc][0], bh[nc][1]);
                    mma8(acc[mt][nc], al[mt], bh[nc][0], bh[nc][1]);
                }
        }
        __syncthreads();
        buf ^= 1;
    }

    #pragma unroll
    for (int mt = 0; mt < 4; mt++) {
        int row = m0 + wm * 64 + mt * 16 + g;
        #pragma unroll
        for (int nc = 0; nc < 4; nc++) {
            int col = n0 + wn * 32 + nc * 8 + 2 * t;
            float b0v = bias[col], b1v = bias[col + 1];
            *(float2*)(C + (size_t)row * ED + col) =
                make_float2(acc[mt][nc][0] + b0v, acc[mt][nc][1] + b1v);
            *(float2*)(C + (size_t)(row + 8) * ED + col) =
                make_float2(acc[mt][nc][2] + b0v, acc[mt][nc][3] + b1v);
        }
    }
}

// ---------------------------------------------------------------------------
// Flash attention. 256 threads (8 warps), 128-q tile per CTA, grid (16,16,2).
// cp.async double-buffered K/V (dynamic smem 70KB). 1-mma S + 1-mma PV.
// P kept in registers, re-laid out C-frag -> A-frag via quad shuffles.
// P RNE-rounded BEFORE the row-sum so its rounding bias cancels in o/l.
// Residual (+x) fused into epilogue.
// ---------------------------------------------------------------------------
#define PK  68
#define PVp 72
#define KSTG (64 * PK)
#define VSTG (64 * PVp)

__global__ void __launch_bounds__(256)
attn_tc(const float* __restrict__ Q, const float* __restrict__ K,
        const float* __restrict__ V, const float* __restrict__ X,
        float* __restrict__ ctx)
{
    extern __shared__ float smem[];
    float* sK = smem;               // [2][64*PK]
    float* sV = smem + 2 * KSTG;    // [2][64*PVp]

    const int tid = threadIdx.x;
    const int w = tid >> 5, lane = tid & 31, g = lane >> 2, t = lane & 3;
    const int qt = blockIdx.x, h = blockIdx.y, b = blockIdx.z;
    const int qrow0 = b * SEQ + qt * 128;
    const int coff  = h * HD;

    // Q fragments straight from gmem, pre-scaled, RNE tf32.
    uint32_t qh[8][4];
    {
        const int r0 = qrow0 + w * 16 + g;
        #pragma unroll
        for (int kc = 0; kc < 8; kc++) {
            qh[kc][0] = f2tf(0.125f * Q[(size_t)r0 * ED + coff + kc * 8 + t]);
            qh[kc][1] = f2tf(0.125f * Q[(size_t)(r0 + 8) * ED + coff + kc * 8 + t]);
            qh[kc][2] = f2tf(0.125f * Q[(size_t)r0 * ED + coff + kc * 8 + t + 4]);
            qh[kc][3] = f2tf(0.125f * Q[(size_t)(r0 + 8) * ED + coff + kc * 8 + t + 4]);
        }
    }

    // stage kt=0
    {
        const int krow0 = b * SEQ;
        #pragma unroll
        for (int i = 0; i < 4; i++) {
            int id = tid + i * 256;
            int r = id >> 4, c4 = (id & 15) << 2;
            cpa16(sK + r * PK + c4,  K + (size_t)(krow0 + r) * ED + coff + c4);
            cpa16(sV + r * PVp + c4, V + (size_t)(krow0 + r) * ED + coff + c4);
        }
        CP_COMMIT();
    }

    float m1 = -1e30f, m2 = -1e30f, l1 = 0.f, l2 = 0.f;
    float o[8][4] = {};

    int buf = 0;
    for (int kt = 0; kt < SEQ / 64; kt++) {
        const bool more = (kt + 1 < SEQ / 64);
        if (more) {
            const int krow0 = b * SEQ + (kt + 1) * 64;
            float* dK = sK + (buf ^ 1) * KSTG;
            float* dV = sV + (buf ^ 1) * VSTG;
            #pragma unroll
            for (int i = 0; i < 4; i++) {
                int id = tid + i * 256;
                int r = id >> 4, c4 = (id & 15) << 2;
                cpa16(dK + r * PK + c4,  K + (size_t)(krow0 + r) * ED + coff + c4);
                cpa16(dV + r * PVp + c4, V + (size_t)(krow0 + r) * ED + coff + c4);
            }
            CP_COMMIT();
            CP_WAIT1();
        } else {
            CP_WAIT0();
        }
        __syncthreads();

        const float* cK = sK + buf * KSTG;
        const float* cV = sV + buf * VSTG;

        // S = Q @ K^T  (K raw fp32 bits -> tf32 truncation; scale-invariant in softmax)
        float s[8][4] = {};
        #pragma unroll
        for (int kc = 0; kc < 8; kc++) {
            #pragma unroll
            for (int nc = 0; nc < 8; nc++) {
                uint32_t b0 = __float_as_uint(cK[(nc * 8 + g) * PK + kc * 8 + t]);
                uint32_t b1 = __float_as_uint(cK[(nc * 8 + g) * PK + kc * 8 + t + 4]);
                mma8(s[nc], qh[kc], b0, b1);
            }
        }

        // online softmax (rows g, g+8; reduce across quad)
        float tm1 = -1e30f, tm2 = -1e30f;
        #pragma unroll
        for (int nc = 0; nc < 8; nc++) {
            tm1 = fmaxf(tm1, fmaxf(s[nc][0], s[nc][1]));
            tm2 = fmaxf(tm2, fmaxf(s[nc][2], s[nc][3]));
        }
        tm1 = fmaxf(tm1, __shfl_xor_sync(0xffffffffu, tm1, 1));
        tm1 = fmaxf(tm1, __shfl_xor_sync(0xffffffffu, tm1, 2));
        tm2 = fmaxf(tm2, __shfl_xor_sync(0xffffffffu, tm2, 1));
        tm2 = fmaxf(tm2, __shfl_xor_sync(0xffffffffu, tm2, 2));

        float mn1 = fmaxf(m1, tm1), mn2 = fmaxf(m2, tm2);
        float c1 = __expf(m1 - mn1), c2 = __expf(m2 - mn2);
        m1 = mn1; m2 = mn2;

        float rs1 = 0.f, rs2 = 0.f;
        #pragma unroll
        for (int nc = 0; nc < 8; nc++) {
            // RNE-round P BEFORE summing so rounding bias cancels in o/l
            s[nc][0] = __uint_as_float(f2tf(__expf(s[nc][0] - mn1)));
            s[nc][1] = __uint_as_float(f2tf(__expf(s[nc][1] - mn1)));
            s[nc][2] = __uint_as_float(f2tf(__expf(s[nc][2] - mn2)));
            s[nc][3] = __uint_as_float(f2tf(__expf(s[nc][3] - mn2)));
            rs1 += s[nc][0] + s[nc][1];
            rs2 += s[nc][2] + s[nc][3];
        }
        rs1 += __shfl_xor_sync(0xffffffffu, rs1, 1);
        rs1 += __shfl_xor_sync(0xffffffffu, rs1, 2);
        rs2 += __shfl_xor_sync(0xffffffffu, rs2, 1);
        rs2 += __shfl_xor_sync(0xffffffffu, rs2, 2);
        l1 = l1 * c1 + rs1;
        l2 = l2 * c2 + rs2;
        #pragma unroll
        for (int nc = 0; nc < 8; nc++) {
            o[nc][0] *= c1; o[nc][1] *= c1;
            o[nc][2] *= c2; o[nc][3] *= c2;
        }

        // O += P @ V: rebuild A-frags from C-frag layout with quad shuffles.
        // C-frag: lane t holds cols {2t,2t+1}; A-frag needs cols {t,t+4}.
        #pragma unroll
        for (int kc = 0; kc < 8; kc++) {
            const int src = t >> 1;
            uint32_t a[4];
            float v0, v1;
            v0 = __shfl_sync(0xffffffffu, s[kc][0], src,     4);
            v1 = __shfl_sync(0xffffffffu, s[kc][1], src,     4);
            a[0] = __float_as_uint((t & 1) ? v1 : v0);
            v0 = __shfl_sync(0xffffffffu, s[kc][2], src,     4);
            v1 = __shfl_sync(0xffffffffu, s[kc][3], src,     4);
            a[1] = __float_as_uint((t & 1) ? v1 : v0);
            v0 = __shfl_sync(0xffffffffu, s[kc][0], src + 2, 4);
            v1 = __shfl_sync(0xffffffffu, s[kc][1], src + 2, 4);
            a[2] = __float_as_uint((t & 1) ? v1 : v0);
            v0 = __shfl_sync(0xffffffffu, s[kc][2], src + 2, 4);
            v1 = __shfl_sync(0xffffffffu, s[kc][3], src + 2, 4);
            a[3] = __float_as_uint((t & 1) ? v1 : v0);

            #pragma unroll
            for (int nc = 0; nc < 8; nc++) {
                uint32_t b0 = __float_as_uint(cV[(kc * 8 + t    ) * PVp + nc * 8 + g]);
                uint32_t b1 = __float_as_uint(cV[(kc * 8 + t + 4) * PVp + nc * 8 + g]);
                mma8(o[nc], a, b0, b1);
            }
        }

        __syncthreads();   // all reads of buf done before next iter's cp.async reuses it
        buf ^= 1;
    }

    const float i1 = 1.f / l1, i2 = 1.f / l2;
    const int r0 = qrow0 + w * 16 + g;
    #pragma unroll
    for (int nc = 0; nc < 8; nc++) {
        int col = coff + nc * 8 + 2 * t;
        float2 x0 = *(const float2*)(X + (size_t)r0 * ED + col);
        float2 x1 = *(const float2*)(X + (size_t)(r0 + 8) * ED + col);
        *(float2*)(ctx + (size_t)r0 * ED + col) =
            make_float2(o[nc][0] * i1 + x0.x, o[nc][1] * i1 + x0.y);
        *(float2*)(ctx + (size_t)(r0 + 8) * ED + col) =
            make_float2(o[nc][2] * i2 + x1.x, o[nc][3] * i2 + x1.y);
    }
}

// ---------------------------------------------------------------------------
extern "C" void kernel_launch(void* const* d_in, const int* in_sizes, int n_in,
                              void* d_out, int out_size)
{
    const float* x  = (const float*)d_in[0];
    const float* wq = (const float*)d_in[1];
    const float* bq = (const float*)d_in[2];
    const float* wk = (const float*)d_in[3];
    const float* bk = (const float*)d_in[4];
    const float* wv = (const float*)d_in[5];
    const float* bv = (const float*)d_in[6];
    const float* wo = (const float*)d_in[7];
    const float* bo = (const float*)d_in[8];
    float* out = (float*)d_out;

    float *Qp, *Kp, *Vp, *Cp;
    cudaGetSymbolAddress((void**)&Qp, g_Q);
    cudaGetSymbolAddress((void**)&Kp, g_K);
    cudaGetSymbolAddress((void**)&Vp, g_V);
    cudaGetSymbolAddress((void**)&Cp, g_C);

    const int attn_smem = (2 * KSTG + 2 * VSTG) * (int)sizeof(float);  // 71680
    cudaFuncSetAttribute(attn_tc, cudaFuncAttributeMaxDynamicSharedMemorySize, attn_smem);

    dim3 ggrid(ED / 128, MTOT / 128);   // (8, 32)

    gemm_tc<<<ggrid, 256>>>(x, wq, bq, Qp);
    gemm_tc<<<ggrid, 256>>>(x, wk, bk, Kp);
    gemm_tc<<<ggrid, 256>>>(x, wv, bv, Vp);

    // ctx = attention(Q,K,V) + x   (residual fused)
    attn_tc<<<dim3(SEQ / 128, NH, BATCH), 256, attn_smem>>>(Qp, Kp, Vp, x, Cp);

    // out = ctx @ w_o + b_o
    gemm_tc<<<ggrid, 256>>>(Cp, wo, bo, out);
}

// round 6
// speedup vs baseline: 5.1109x; 1.3532x over previous
#include <cuda_runtime.h>
#include <cuda_fp16.h>
#include <stdint.h>

#define ED   1024
#define NH   16
#define HD   64
#define SEQ  2048
#define BATCH 2
#define MTOT (BATCH*SEQ)

// scratch (__device__ globals: allocation-free rule)
__device__ __half g_Qh[MTOT * ED];
__device__ __half g_Kh[MTOT * ED];
__device__ __half g_Vh[MTOT * ED];
__device__ __half g_xh[MTOT * ED], g_xl[MTOT * ED];
__device__ __half g_ch[MTOT * ED], g_cl[MTOT * ED];
__device__ __half g_wh[4][ED * ED], g_wl[4][ED * ED];   // K-major [N][K], scaled x32

// ---------------------------------------------------------------------------
// helpers
// ---------------------------------------------------------------------------
__device__ __forceinline__ uint32_t packh(__half a, __half b) {
    return (uint32_t)__half_as_ushort(a) | ((uint32_t)__half_as_ushort(b) << 16);
}
__device__ __forceinline__ void mma16(float* d, const uint32_t* a, uint32_t b0, uint32_t b1) {
    asm volatile(
        "mma.sync.aligned.m16n8k16.row.col.f32.f16.f16.f32 "
        "{%0,%1,%2,%3}, {%4,%5,%6,%7}, {%8,%9}, {%0,%1,%2,%3};\n"
        : "+f"(d[0]), "+f"(d[1]), "+f"(d[2]), "+f"(d[3])
        : "r"(a[0]), "r"(a[1]), "r"(a[2]), "r"(a[3]), "r"(b0), "r"(b1));
}
__device__ __forceinline__ void cpa16(void* sdst, const void* gsrc) {
    uint32_t sa = (uint32_t)__cvta_generic_to_shared(sdst);
    asm volatile("cp.async.cg.shared.global [%0], [%1], 16;\n" :: "r"(sa), "l"(gsrc));
}
#define CP_COMMIT() asm volatile("cp.async.commit_group;\n" ::: "memory")
#define CP_WAIT1()  asm volatile("cp.async.wait_group 1;\n" ::: "memory")
#define CP_WAIT0()  asm volatile("cp.async.wait_group 0;\n" ::: "memory")

__device__ __forceinline__ void ldmx4t(uint32_t& r0, uint32_t& r1, uint32_t& r2,
                                       uint32_t& r3, uint32_t saddr) {
    asm volatile("ldmatrix.sync.aligned.m8n8.x4.trans.shared.b16 {%0,%1,%2,%3}, [%4];"
                 : "=r"(r0), "=r"(r1), "=r"(r2), "=r"(r3) : "r"(saddr));
}

// ---------------------------------------------------------------------------
// split kernels
// ---------------------------------------------------------------------------
__global__ void __launch_bounds__(256)
asplit(const float* __restrict__ A, __half* __restrict__ oh, __half* __restrict__ ol)
{
    int i = blockIdx.x * 256 + threadIdx.x;            // 4 elems per thread
    float4 v = ((const float4*)A)[i];
    __half h0 = __float2half_rn(v.x), h1 = __float2half_rn(v.y);
    __half h2 = __float2half_rn(v.z), h3 = __float2half_rn(v.w);
    __half l0 = __float2half_rn(v.x - __half2float(h0));
    __half l1 = __float2half_rn(v.y - __half2float(h1));
    __half l2 = __float2half_rn(v.z - __half2float(h2));
    __half l3 = __float2half_rn(v.w - __half2float(h3));
    ((uint2*)oh)[i] = make_uint2(packh(h0, h1), packh(h2, h3));
    ((uint2*)ol)[i] = make_uint2(packh(l0, l1), packh(l2, l3));
}
// W [K][N] fp32 -> (32*W) split hi/lo, K-major [N][K] half
__global__ void __launch_bounds__(256)
wsplit(const float* __restrict__ W, __half* __restrict__ bh, __half* __restrict__ bl)
{
    __shared__ float t[32][33];
    int k0 = blockIdx.x * 32, n0 = blockIdx.y * 32;
    int tx = threadIdx.x, ty = threadIdx.y;            // (32, 8)
    #pragma unroll
    for (int i = 0; i < 4; i++)
        t[ty + 8 * i][tx] = W[(size_t)(k0 + ty + 8 * i) * ED + n0 + tx];
    __syncthreads();
    #pragma unroll
    for (int i = 0; i < 4; i++) {
        float v = 32.f * t[tx][ty + 8 * i];            // W[k0+tx][n0+ty+8i] * 32
        __half h = __float2half_rn(v);
        __half l = __float2half_rn(v - __half2float(h));
        bh[(size_t)(n0 + ty + 8 * i) * ED + k0 + tx] = h;
        bl[(size_t)(n0 + ty + 8 * i) * ED + k0 + tx] = l;
    }
}

// ---------------------------------------------------------------------------
// fp16 GEMM: acc = A @ (32W)^T (3-mma hi/lo split, fp32 accum);
// out = acc*sa + bias*sb, half or float.
// 128x128 tile, k-chunk 32, 8 warps (2x4), warp tile 64x32, cp.async dbuf.
// Pitch 40 halves -> frag LDS conflict-free ((20g+t) mod 32 distinct).
// ---------------------------------------------------------------------------
#define GP   40
#define GSTG (128 * GP)                     // halves per array per stage
#define GSMEM (2 * 4 * GSTG * 2)            // bytes = 81920

template <bool HALF_OUT>
__global__ void __launch_bounds__(256)
gemm_h(const __half* __restrict__ Ah, const __half* __restrict__ Al,
       const __half* __restrict__ Bh, const __half* __restrict__ Bl,
       const float* __restrict__ bias, void* __restrict__ outp,
       float sa, float sb)
{
    extern __shared__ __half hsm[];
    const int tid = threadIdx.x;
    const int w = tid >> 5, lane = tid & 31, g = lane >> 2, t = lane & 3;
    const int wm = w >> 2, wn = w & 3;
    const int m0 = blockIdx.y * 128, n0 = blockIdx.x * 128;

    float acc[4][4][4] = {};

    auto stage = [&](int c, int s) {
        __half* base = hsm + (size_t)s * 4 * GSTG;
        const int k0 = c * 32;
        #pragma unroll
        for (int i = 0; i < 2; i++) {
            int id = i * 256 + tid;
            int r = id >> 2, c8 = (id & 3) << 3;
            cpa16(base + r * GP + c8,            Ah + (size_t)(m0 + r) * ED + k0 + c8);
            cpa16(base + GSTG + r * GP + c8,     Al + (size_t)(m0 + r) * ED + k0 + c8);
            cpa16(base + 2 * GSTG + r * GP + c8, Bh + (size_t)(n0 + r) * ED + k0 + c8);
            cpa16(base + 3 * GSTG + r * GP + c8, Bl + (size_t)(n0 + r) * ED + k0 + c8);
        }
        CP_COMMIT();
    };

    stage(0, 0);
    int buf = 0;
    for (int c = 0; c < 32; c++) {
        if (c + 1 < 32) { stage(c + 1, buf ^ 1); CP_WAIT1(); }
        else            { CP_WAIT0(); }
        __syncthreads();

        const __half* cAh = hsm + (size_t)buf * 4 * GSTG;
        const __half* cAl = cAh + GSTG;
        const __half* cBh = cAh + 2 * GSTG;
        const __half* cBl = cAh + 3 * GSTG;

        #pragma unroll
        for (int ks = 0; ks < 2; ks++) {
            const int kc = ks * 16 + 2 * t;
            uint32_t ah[4][4], al[4][4];
            #pragma unroll
            for (int mt = 0; mt < 4; mt++) {
                int row = wm * 64 + mt * 16;
                ah[mt][0] = *(const uint32_t*)(cAh + (row + g    ) * GP + kc);
                ah[mt][1] = *(const uint32_t*)(cAh + (row + g + 8) * GP + kc);
                ah[mt][2] = *(const uint32_t*)(cAh + (row + g    ) * GP + kc + 8);
                ah[mt][3] = *(const uint32_t*)(cAh + (row + g + 8) * GP + kc + 8);
                al[mt][0] = *(const uint32_t*)(cAl + (row + g    ) * GP + kc);
                al[mt][1] = *(const uint32_t*)(cAl + (row + g + 8) * GP + kc);
                al[mt][2] = *(const uint32_t*)(cAl + (row + g    ) * GP + kc + 8);
                al[mt][3] = *(const uint32_t*)(cAl + (row + g + 8) * GP + kc + 8);
            }
            uint32_t bh[4][2], bl[4][2];
            #pragma unroll
            for (int nc = 0; nc < 4; nc++) {
                int col = wn * 32 + nc * 8 + g;
                bh[nc][0] = *(const uint32_t*)(cBh + col * GP + kc);
                bh[nc][1] = *(const uint32_t*)(cBh + col * GP + kc + 8);
                bl[nc][0] = *(const uint32_t*)(cBl + col * GP + kc);
                bl[nc][1] = *(const uint32_t*)(cBl + col * GP + kc + 8);
            }
            #pragma unroll
            for (int mt = 0; mt < 4; mt++)
                #pragma unroll
                for (int nc = 0; nc < 4; nc++) {
                    mma16(acc[mt][nc], ah[mt], bh[nc][0], bh[nc][1]);
                    mma16(acc[mt][nc], al[mt], bh[nc][0], bh[nc][1]);
                    mma16(acc[mt][nc], ah[mt], bl[nc][0], bl[nc][1]);
                }
        }
        __syncthreads();
        buf ^= 1;
    }

    #pragma unroll
    for (int mt = 0; mt < 4; mt++) {
        int row = m0 + wm * 64 + mt * 16 + g;
        #pragma unroll
        for (int nc = 0; nc < 4; nc++) {
            int col = n0 + wn * 32 + nc * 8 + 2 * t;
            float b0 = bias[col] * sb, b1 = bias[col + 1] * sb;
            float v00 = acc[mt][nc][0] * sa + b0, v01 = acc[mt][nc][1] * sa + b1;
            float v10 = acc[mt][nc][2] * sa + b0, v11 = acc[mt][nc][3] * sa + b1;
            if (HALF_OUT) {
                __half* O = (__half*)outp;
                *(uint32_t*)(O + (size_t)row * ED + col) =
                    packh(__float2half_rn(v00), __float2half_rn(v01));
                *(uint32_t*)(O + (size_t)(row + 8) * ED + col) =
                    packh(__float2half_rn(v10), __float2half_rn(v11));
            } else {
                float* O = (float*)outp;
                *(float2*)(O + (size_t)row * ED + col)       = make_float2(v00, v01);
                *(float2*)(O + (size_t)(row + 8) * ED + col) = make_float2(v10, v11);
            }
        }
    }
}

// ---------------------------------------------------------------------------
// fp16 flash attention. 256 thr (8 warps x 16 q rows), 128-q tile, grid (16,16,2).
// Q pre-scaled fp16 from the Q-GEMM. K/V fp16 via cp.async double buffer.
// S: 1 mma k16 per (kc,nc). P: C-frag == A-frag col pairs -> no shuffles.
// V B-frags via ldmatrix.x4.trans. Epilogue: +x residual, write split h/l.
// ---------------------------------------------------------------------------
#define PH   72
#define HSTG (64 * PH)                      // halves per tile array

__global__ void __launch_bounds__(256)
attn_h(const __half* __restrict__ Q, const __half* __restrict__ K,
       const __half* __restrict__ V, const float* __restrict__ X,
       __half* __restrict__ CH, __half* __restrict__ CL)
{
    extern __shared__ __half hsm[];
    __half* sK = hsm;                       // [2][HSTG]
    __half* sV = hsm + 2 * HSTG;            // [2][HSTG]

    const int tid = threadIdx.x;
    const int w = tid >> 5, lane = tid & 31, g = lane >> 2, t = lane & 3;
    const int qt = blockIdx.x, h = blockIdx.y, b = blockIdx.z;
    const int qrow0 = b * SEQ + qt * 128;
    const int coff  = h * HD;

    // ldmatrix per-lane row offset (bytes) within a 16x16 V block
    const int matq = lane >> 3;
    const uint32_t ldmoff = (uint32_t)((((matq & 1) * 8 + (lane & 7)) * PH +
                                        (matq >> 1) * 8) * 2);
    const uint32_t sVu = (uint32_t)__cvta_generic_to_shared(sV);

    // Q fragments (already x0.125, fp16)
    uint32_t qf[4][4];
    {
        const int r0 = qrow0 + w * 16 + g;
        #pragma unroll
        for (int kc = 0; kc < 4; kc++) {
            int c0 = coff + kc * 16 + 2 * t;
            qf[kc][0] = *(const uint32_t*)(Q + (size_t)r0 * ED + c0);
            qf[kc][1] = *(const uint32_t*)(Q + (size_t)(r0 + 8) * ED + c0);
            qf[kc][2] = *(const uint32_t*)(Q + (size_t)r0 * ED + c0 + 8);
            qf[kc][3] = *(const uint32_t*)(Q + (size_t)(r0 + 8) * ED + c0 + 8);
        }
    }

    auto stage = [&](int kt, int s) {
        const int krow0 = b * SEQ + kt * 64;
        __half* dK = sK + s * HSTG;
        __half* dV = sV + s * HSTG;
        #pragma unroll
        for (int i = 0; i < 2; i++) {
            int id = i * 256 + tid;
            int r = id >> 3, c8 = (id & 7) << 3;
            cpa16(dK + r * PH + c8, K + (size_t)(krow0 + r) * ED + coff + c8);
            cpa16(dV + r * PH + c8, V + (size_t)(krow0 + r) * ED + coff + c8);
        }
        CP_COMMIT();
    };

    stage(0, 0);

    float m1 = -1e30f, m2 = -1e30f, l1 = 0.f, l2 = 0.f;
    float o[8][4] = {};

    int buf = 0;
    for (int kt = 0; kt < SEQ / 64; kt++) {
        if (kt + 1 < SEQ / 64) { stage(kt + 1, buf ^ 1); CP_WAIT1(); }
        else                   { CP_WAIT0(); }
        __syncthreads();

        const __half* cK = sK + buf * HSTG;
        const uint32_t cVu = sVu + (uint32_t)(buf * HSTG * 2);

        // S = Q @ K^T
        float s[8][4] = {};
        #pragma unroll
        for (int kc = 0; kc < 4; kc++) {
            const int kcc = kc * 16 + 2 * t;
            #pragma unroll
            for (int nc = 0; nc < 8; nc++) {
                uint32_t b0 = *(const uint32_t*)(cK + (nc * 8 + g) * PH + kcc);
                uint32_t b1 = *(const uint32_t*)(cK + (nc * 8 + g) * PH + kcc + 8);
                mma16(s[nc], qf[kc], b0, b1);
            }
        }

        // online softmax (rows g, g+8; quad reduce)
        float tm1 = -1e30f, tm2 = -1e30f;
        #pragma unroll
        for (int nc = 0; nc < 8; nc++) {
            tm1 = fmaxf(tm1, fmaxf(s[nc][0], s[nc][1]));
            tm2 = fmaxf(tm2, fmaxf(s[nc][2], s[nc][3]));
        }
        tm1 = fmaxf(tm1, __shfl_xor_sync(0xffffffffu, tm1, 1));
        tm1 = fmaxf(tm1, __shfl_xor_sync(0xffffffffu, tm1, 2));
        tm2 = fmaxf(tm2, __shfl_xor_sync(0xffffffffu, tm2, 1));
        tm2 = fmaxf(tm2, __shfl_xor_sync(0xffffffffu, tm2, 2));

        float mn1 = fmaxf(m1, tm1), mn2 = fmaxf(m2, tm2);
        float c1 = __expf(m1 - mn1), c2 = __expf(m2 - mn2);
        m1 = mn1; m2 = mn2;

        // P -> fp16 (rounded BEFORE row-sum so bias cancels in o/l)
        uint32_t p0[8], p1[8];
        float rs1 = 0.f, rs2 = 0.f;
        #pragma unroll
        for (int nc = 0; nc < 8; nc++) {
            __half h0 = __float2half_rn(__expf(s[nc][0] - mn1));
            __half h1 = __float2half_rn(__expf(s[nc][1] - mn1));
            __half h2 = __float2half_rn(__expf(s[nc][2] - mn2));
            __half h3 = __float2half_rn(__expf(s[nc][3] - mn2));
            p0[nc] = packh(h0, h1);
            p1[nc] = packh(h2, h3);
            rs1 += __half2float(h0) + __half2float(h1);
            rs2 += __half2float(h2) + __half2float(h3);
        }
        rs1 += __shfl_xor_sync(0xffffffffu, rs1, 1);
        rs1 += __shfl_xor_sync(0xffffffffu, rs1, 2);
        rs2 += __shfl_xor_sync(0xffffffffu, rs2, 1);
        rs2 += __shfl_xor_sync(0xffffffffu, rs2, 2);
        l1 = l1 * c1 + rs1;
        l2 = l2 * c2 + rs2;
        #pragma unroll
        for (int nc = 0; nc < 8; nc++) {
            o[nc][0] *= c1; o[nc][1] *= c1;
            o[nc][2] *= c2; o[nc][3] *= c2;
        }

        // O += P @ V  (A-frag = C-frag pairs; V via ldmatrix.x4.trans)
        #pragma unroll
        for (int kc = 0; kc < 4; kc++) {
            uint32_t a[4] = { p0[2 * kc], p1[2 * kc], p0[2 * kc + 1], p1[2 * kc + 1] };
            #pragma unroll
            for (int np = 0; np < 4; np++) {
                uint32_t r0, r1, r2, r3;
                uint32_t addr = cVu + (uint32_t)((kc * 16 * PH + np * 16) * 2) + ldmoff;
                ldmx4t(r0, r1, r2, r3, addr);
                mma16(o[2 * np],     a, r0, r1);
                mma16(o[2 * np + 1], a, r2, r3);
            }
        }

        __syncthreads();
        buf ^= 1;
    }

    // epilogue: ctx = o/l + x, split h/l for the O-GEMM
    const float i1 = 1.f / l1, i2 = 1.f / l2;
    const int r0 = qrow0 + w * 16 + g;
    #pragma unroll
    for (int nc = 0; nc < 8; nc++) {
        int col = coff + nc * 8 + 2 * t;
        float2 x0 = *(const float2*)(X + (size_t)r0 * ED + col);
        float2 x1 = *(const float2*)(X + (size_t)(r0 + 8) * ED + col);
        float v00 = o[nc][0] * i1 + x0.x, v01 = o[nc][1] * i1 + x0.y;
        float v10 = o[nc][2] * i2 + x1.x, v11 = o[nc][3] * i2 + x1.y;
        __half h00 = __float2half_rn(v00), h01 = __float2half_rn(v01);
        __half h10 = __float2half_rn(v10), h11 = __float2half_rn(v11);
        *(uint32_t*)(CH + (size_t)r0 * ED + col) = packh(h00, h01);
        *(uint32_t*)(CH + (size_t)(r0 + 8) * ED + col) = packh(h10, h11);
        *(uint32_t*)(CL + (size_t)r0 * ED + col) =
            packh(__float2half_rn(v00 - __half2float(h00)),
                  __float2half_rn(v01 - __half2float(h01)));
        *(uint32_t*)(CL + (size_t)(r0 + 8) * ED + col) =
            packh(__float2half_rn(v10 - __half2float(h10)),
                  __float2half_rn(v11 - __half2float(h11)));
    }
}

// ---------------------------------------------------------------------------
extern "C" void kernel_launch(void* const* d_in, const int* in_sizes, int n_in,
                              void* d_out, int out_size)
{
    const float* x  = (const float*)d_in[0];
    const float* wq = (const float*)d_in[1];
    const float* bq = (const float*)d_in[2];
    const float* wk = (const float*)d_in[3];
    const float* bk = (const float*)d_in[4];
    const float* wv = (const float*)d_in[5];
    const float* bv = (const float*)d_in[6];
    const float* wo = (const float*)d_in[7];
    const float* bo = (const float*)d_in[8];
    float* out = (float*)d_out;

    __half *Qh, *Kh, *Vh, *xh, *xl, *ch, *cl, *wh, *wl;
    cudaGetSymbolAddress((void**)&Qh, g_Qh);
    cudaGetSymbolAddress((void**)&Kh, g_Kh);
    cudaGetSymbolAddress((void**)&Vh, g_Vh);
    cudaGetSymbolAddress((void**)&xh, g_xh);
    cudaGetSymbolAddress((void**)&xl, g_xl);
    cudaGetSymbolAddress((void**)&ch, g_ch);
    cudaGetSymbolAddress((void**)&cl, g_cl);
    cudaGetSymbolAddress((void**)&wh, g_wh);
    cudaGetSymbolAddress((void**)&wl, g_wl);

    cudaFuncSetAttribute(gemm_h<true>,  cudaFuncAttributeMaxDynamicSharedMemorySize, GSMEM);
    cudaFuncSetAttribute(gemm_h<false>, cudaFuncAttributeMaxDynamicSharedMemorySize, GSMEM);
    const int attn_smem = 4 * HSTG * (int)sizeof(__half);   // 36864
    cudaFuncSetAttribute(attn_h, cudaFuncAttributeMaxDynamicSharedMemorySize, attn_smem);

    // splits
    asplit<<<MTOT * ED / 1024, 256>>>(x, xh, xl);
    dim3 wgrid(ED / 32, ED / 32), wblk(32, 8);
    wsplit<<<wgrid, wblk>>>(wq, wh + 0 * (size_t)ED * ED, wl + 0 * (size_t)ED * ED);
    wsplit<<<wgrid, wblk>>>(wk, wh + 1 * (size_t)ED * ED, wl + 1 * (size_t)ED * ED);
    wsplit<<<wgrid, wblk>>>(wv, wh + 2 * (size_t)ED * ED, wl + 2 * (size_t)ED * ED);
    wsplit<<<wgrid, wblk>>>(wo, wh + 3 * (size_t)ED * ED, wl + 3 * (size_t)ED * ED);

    dim3 ggrid(ED / 128, MTOT / 128);   // (8, 32)
    // Q = (x@Wq + bq)*0.125 as half (W stored x32 -> sa = 1/256)
    gemm_h<true><<<ggrid, 256, GSMEM>>>(xh, xl, wh + 0 * (size_t)ED * ED,
                                        wl + 0 * (size_t)ED * ED, bq, Qh,
                                        1.f / 256.f, 0.125f);
    gemm_h<true><<<ggrid, 256, GSMEM>>>(xh, xl, wh + 1 * (size_t)ED * ED,
                                        wl + 1 * (size_t)ED * ED, bk, Kh,
                                        1.f / 32.f, 1.f);
    gemm_h<true><<<ggrid, 256, GSMEM>>>(xh, xl, wh + 2 * (size_t)ED * ED,
                                        wl + 2 * (size_t)ED * ED, bv, Vh,
                                        1.f / 32.f, 1.f);

    attn_h<<<dim3(SEQ / 128, NH, BATCH), 256, attn_smem>>>(Qh, Kh, Vh, x, ch, cl);

    gemm_h<false><<<ggrid, 256, GSMEM>>>(ch, cl, wh + 3 * (size_t)ED * ED,
                                         wl + 3 * (size_t)ED * ED, bo, out,
                                         1.f / 32.f, 1.f);
}

// round 7
// speedup vs baseline: 8.4506x; 1.6534x over previous
#include <cuda_runtime.h>
#include <cuda_fp16.h>
#include <stdint.h>

#define ED   1024
#define NH   16
#define HD   64
#define SEQ  2048
#define BATCH 2
#define MTOT (BATCH*SEQ)

// scratch (__device__ globals: allocation-free rule)
__device__ __half g_Qh[MTOT * ED];
__device__ __half g_Kh[MTOT * ED];
__device__ __half g_Vh[MTOT * ED];
__device__ __half g_xh[MTOT * ED];
__device__ __half g_ch[MTOT * ED];
__device__ __half g_wh[4][ED * ED];        // K-major [N][K]; [0..2] packed QKV

// ---------------------------------------------------------------------------
// helpers
// ---------------------------------------------------------------------------
__device__ __forceinline__ uint32_t packh(__half a, __half b) {
    return (uint32_t)__half_as_ushort(a) | ((uint32_t)__half_as_ushort(b) << 16);
}
__device__ __forceinline__ void mma16(float* d, const uint32_t* a, uint32_t b0, uint32_t b1) {
    asm volatile(
        "mma.sync.aligned.m16n8k16.row.col.f32.f16.f16.f32 "
        "{%0,%1,%2,%3}, {%4,%5,%6,%7}, {%8,%9}, {%0,%1,%2,%3};\n"
        : "+f"(d[0]), "+f"(d[1]), "+f"(d[2]), "+f"(d[3])
        : "r"(a[0]), "r"(a[1]), "r"(a[2]), "r"(a[3]), "r"(b0), "r"(b1));
}
__device__ __forceinline__ void cpa16(void* sdst, const void* gsrc) {
    uint32_t sa = (uint32_t)__cvta_generic_to_shared(sdst);
    asm volatile("cp.async.cg.shared.global [%0], [%1], 16;\n" :: "r"(sa), "l"(gsrc));
}
#define CP_COMMIT() asm volatile("cp.async.commit_group;\n" ::: "memory")
#define CP_WAIT1()  asm volatile("cp.async.wait_group 1;\n" ::: "memory")
#define CP_WAIT0()  asm volatile("cp.async.wait_group 0;\n" ::: "memory")

__device__ __forceinline__ void ldmx4t(uint32_t& r0, uint32_t& r1, uint32_t& r2,
                                       uint32_t& r3, uint32_t saddr) {
    asm volatile("ldmatrix.sync.aligned.m8n8.x4.trans.shared.b16 {%0,%1,%2,%3}, [%4];"
                 : "=r"(r0), "=r"(r1), "=r"(r2), "=r"(r3) : "r"(saddr));
}

// ---------------------------------------------------------------------------
// rounding kernels (fp32 -> fp16 RNE)
// ---------------------------------------------------------------------------
__global__ void __launch_bounds__(256)
around(const float* __restrict__ A, __half* __restrict__ oh)
{
    int i = blockIdx.x * 256 + threadIdx.x;            // 4 elems per thread
    float4 v = ((const float4*)A)[i];
    ((uint2*)oh)[i] = make_uint2(packh(__float2half_rn(v.x), __float2half_rn(v.y)),
                                 packh(__float2half_rn(v.z), __float2half_rn(v.w)));
}
// W [K][N] fp32 -> K-major [N][K] fp16
__global__ void __launch_bounds__(256)
wround(const float* __restrict__ W, __half* __restrict__ bh)
{
    __shared__ float t[32][33];
    int k0 = blockIdx.x * 32, n0 = blockIdx.y * 32;
    int tx = threadIdx.x, ty = threadIdx.y;            // (32, 8)
    #pragma unroll
    for (int i = 0; i < 4; i++)
        t[ty + 8 * i][tx] = W[(size_t)(k0 + ty + 8 * i) * ED + n0 + tx];
    __syncthreads();
    #pragma unroll
    for (int i = 0; i < 4; i++)
        bh[(size_t)(n0 + ty + 8 * i) * ED + k0 + tx] = __float2half_rn(t[tx][ty + 8 * i]);
}

// ---------------------------------------------------------------------------
// fp16 GEMM mainloop pieces: 128x128 tile, k-chunk 32, 8 warps (2x4),
// warp tile 64x32, cp.async double buffer. Pitch 40 halves (conflict-free).
// ---------------------------------------------------------------------------
#define GP   40
#define GSTG (128 * GP)                     // halves per array per stage

#define GEMM_MAIN(A_, B_)                                                          \
    __shared__ __half hsm[2][2 * GSTG];                                            \
    const int tid = threadIdx.x;                                                   \
    const int w = tid >> 5, lane = tid & 31, g = lane >> 2, t = lane & 3;          \
    const int wm = w >> 2, wn = w & 3;                                             \
    const int m0 = blockIdx.y * 128;                                               \
    const int nrow0 = blockIdx.x * 128;                                            \
    float acc[4][4][4] = {};                                                       \
    auto stage = [&](int c, int s) {                                               \
        __half* base = hsm[s];                                                     \
        const int k0 = c * 32;                                                     \
        _Pragma("unroll")                                                          \
        for (int i = 0; i < 2; i++) {                                              \
            int id = i * 256 + tid;                                                \
            int r = id >> 2, c8 = (id & 3) << 3;                                   \
            cpa16(base + r * GP + c8,        A_ + (size_t)(m0 + r) * ED + k0 + c8);\
            cpa16(base + GSTG + r * GP + c8, B_ + (size_t)(nrow0 + r) * ED + k0 + c8);\
        }                                                                          \
        CP_COMMIT();                                                               \
    };                                                                             \
    stage(0, 0);                                                                   \
    int buf = 0;                                                                   \
    for (int c = 0; c < 32; c++) {                                                 \
        if (c + 1 < 32) { stage(c + 1, buf ^ 1); CP_WAIT1(); }                     \
        else            { CP_WAIT0(); }                                            \
        __syncthreads();                                                           \
        const __half* cA = hsm[buf];                                               \
        const __half* cB = cA + GSTG;                                              \
        _Pragma("unroll")                                                          \
        for (int ks = 0; ks < 2; ks++) {                                           \
            const int kc = ks * 16 + 2 * t;                                        \
            uint32_t af[4][4];                                                     \
            _Pragma("unroll")                                                      \
            for (int mt = 0; mt < 4; mt++) {                                       \
                int row = wm * 64 + mt * 16;                                       \
                af[mt][0] = *(const uint32_t*)(cA + (row + g    ) * GP + kc);      \
                af[mt][1] = *(const uint32_t*)(cA + (row + g + 8) * GP + kc);      \
                af[mt][2] = *(const uint32_t*)(cA + (row + g    ) * GP + kc + 8);  \
                af[mt][3] = *(const uint32_t*)(cA + (row + g + 8) * GP + kc + 8);  \
            }                                                                      \
            uint32_t bf[4][2];                                                     \
            _Pragma("unroll")                                                      \
            for (int nc = 0; nc < 4; nc++) {                                       \
                int col = wn * 32 + nc * 8 + g;                                    \
                bf[nc][0] = *(const uint32_t*)(cB + col * GP + kc);                \
                bf[nc][1] = *(const uint32_t*)(cB + col * GP + kc + 8);            \
            }                                                                      \
            _Pragma("unroll")                                                      \
            for (int mt = 0; mt < 4; mt++)                                         \
                _Pragma("unroll")                                                  \
                for (int nc = 0; nc < 4; nc++)                                     \
                    mma16(acc[mt][nc], af[mt], bf[nc][0], bf[nc][1]);              \
        }                                                                          \
        __syncthreads();                                                           \
        buf ^= 1;                                                                  \
    }

// fused QKV: B is packed [3072][1024]; seg 0=Q (x0.125, half out), 1=K, 2=V
__global__ void __launch_bounds__(256, 2)
gemm_qkv(const __half* __restrict__ A, const __half* __restrict__ B,
         const float* __restrict__ bq, const float* __restrict__ bk,
         const float* __restrict__ bv,
         __half* __restrict__ Qh, __half* __restrict__ Kh, __half* __restrict__ Vh)
{
    GEMM_MAIN(A, B)

    const int seg = blockIdx.x >> 3;                  // 8 n-blocks per segment
    const int ncol0 = (blockIdx.x & 7) * 128;
    const float* bias = (seg == 0) ? bq : (seg == 1) ? bk : bv;
    __half* O = (seg == 0) ? Qh : (seg == 1) ? Kh : Vh;
    const float sc = (seg == 0) ? 0.125f : 1.0f;

    #pragma unroll
    for (int mt = 0; mt < 4; mt++) {
        int row = m0 + wm * 64 + mt * 16 + g;
        #pragma unroll
        for (int nc = 0; nc < 4; nc++) {
            int col = ncol0 + wn * 32 + nc * 8 + 2 * t;
            float b0 = bias[col], b1 = bias[col + 1];
            *(uint32_t*)(O + (size_t)row * ED + col) =
                packh(__float2half_rn((acc[mt][nc][0] + b0) * sc),
                      __float2half_rn((acc[mt][nc][1] + b1) * sc));
            *(uint32_t*)(O + (size_t)(row + 8) * ED + col) =
                packh(__float2half_rn((acc[mt][nc][2] + b0) * sc),
                      __float2half_rn((acc[mt][nc][3] + b1) * sc));
        }
    }
}

// O projection: float out
__global__ void __launch_bounds__(256, 2)
gemm_o(const __half* __restrict__ A, const __half* __restrict__ B,
       const float* __restrict__ bias, float* __restrict__ out)
{
    GEMM_MAIN(A, B)

    #pragma unroll
    for (int mt = 0; mt < 4; mt++) {
        int row = m0 + wm * 64 + mt * 16 + g;
        #pragma unroll
        for (int nc = 0; nc < 4; nc++) {
            int col = nrow0 + wn * 32 + nc * 8 + 2 * t;
            float b0 = bias[col], b1 = bias[col + 1];
            *(float2*)(out + (size_t)row * ED + col) =
                make_float2(acc[mt][nc][0] + b0, acc[mt][nc][1] + b1);
            *(float2*)(out + (size_t)(row + 8) * ED + col) =
                make_float2(acc[mt][nc][2] + b0, acc[mt][nc][3] + b1);
        }
    }
}

// ---------------------------------------------------------------------------
// fp16 flash attention (R6 structure). 256 thr, 128-q tile, grid (16,16,2).
// Epilogue: ctx = o/l + x  ->  fp16 (single array).
// ---------------------------------------------------------------------------
#define PH   72
#define HSTG (64 * PH)

__global__ void __launch_bounds__(256)
attn_h(const __half* __restrict__ Q, const __half* __restrict__ K,
       const __half* __restrict__ V, const float* __restrict__ X,
       __half* __restrict__ CH)
{
    __shared__ __half hsm[4 * HSTG];
    __half* sK = hsm;                       // [2][HSTG]
    __half* sV = hsm + 2 * HSTG;            // [2][HSTG]

    const int tid = threadIdx.x;
    const int w = tid >> 5, lane = tid & 31, g = lane >> 2, t = lane & 3;
    const int qt = blockIdx.x, h = blockIdx.y, b = blockIdx.z;
    const int qrow0 = b * SEQ + qt * 128;
    const int coff  = h * HD;

    const int matq = lane >> 3;
    const uint32_t ldmoff = (uint32_t)((((matq & 1) * 8 + (lane & 7)) * PH +
                                        (matq >> 1) * 8) * 2);
    const uint32_t sVu = (uint32_t)__cvta_generic_to_shared(sV);

    uint32_t qf[4][4];
    {
        const int r0 = qrow0 + w * 16 + g;
        #pragma unroll
        for (int kc = 0; kc < 4; kc++) {
            int c0 = coff + kc * 16 + 2 * t;
            qf[kc][0] = *(const uint32_t*)(Q + (size_t)r0 * ED + c0);
            qf[kc][1] = *(const uint32_t*)(Q + (size_t)(r0 + 8) * ED + c0);
            qf[kc][2] = *(const uint32_t*)(Q + (size_t)r0 * ED + c0 + 8);
            qf[kc][3] = *(const uint32_t*)(Q + (size_t)(r0 + 8) * ED + c0 + 8);
        }
    }

    auto stage = [&](int kt, int s) {
        const int krow0 = b * SEQ + kt * 64;
        __half* dK = sK + s * HSTG;
        __half* dV = sV + s * HSTG;
        #pragma unroll
        for (int i = 0; i < 2; i++) {
            int id = i * 256 + tid;
            int r = id >> 3, c8 = (id & 7) << 3;
            cpa16(dK + r * PH + c8, K + (size_t)(krow0 + r) * ED + coff + c8);
            cpa16(dV + r * PH + c8, V + (size_t)(krow0 + r) * ED + coff + c8);
        }
        CP_COMMIT();
    };

    stage(0, 0);

    float m1 = -1e30f, m2 = -1e30f, l1 = 0.f, l2 = 0.f;
    float o[8][4] = {};

    int buf = 0;
    for (int kt = 0; kt < SEQ / 64; kt++) {
        if (kt + 1 < SEQ / 64) { stage(kt + 1, buf ^ 1); CP_WAIT1(); }
        else                   { CP_WAIT0(); }
        __syncthreads();

        const __half* cK = sK + buf * HSTG;
        const uint32_t cVu = sVu + (uint32_t)(buf * HSTG * 2);

        float s[8][4] = {};
        #pragma unroll
        for (int kc = 0; kc < 4; kc++) {
            const int kcc = kc * 16 + 2 * t;
            #pragma unroll
            for (int nc = 0; nc < 8; nc++) {
                uint32_t b0 = *(const uint32_t*)(cK + (nc * 8 + g) * PH + kcc);
                uint32_t b1 = *(const uint32_t*)(cK + (nc * 8 + g) * PH + kcc + 8);
                mma16(s[nc], qf[kc], b0, b1);
            }
        }

        float tm1 = -1e30f, tm2 = -1e30f;
        #pragma unroll
        for (int nc = 0; nc < 8; nc++) {
            tm1 = fmaxf(tm1, fmaxf(s[nc][0], s[nc][1]));
            tm2 = fmaxf(tm2, fmaxf(s[nc][2], s[nc][3]));
        }
        tm1 = fmaxf(tm1, __shfl_xor_sync(0xffffffffu, tm1, 1));
        tm1 = fmaxf(tm1, __shfl_xor_sync(0xffffffffu, tm1, 2));
        tm2 = fmaxf(tm2, __shfl_xor_sync(0xffffffffu, tm2, 1));
        tm2 = fmaxf(tm2, __shfl_xor_sync(0xffffffffu, tm2, 2));

        float mn1 = fmaxf(m1, tm1), mn2 = fmaxf(m2, tm2);
        float c1 = __expf(m1 - mn1), c2 = __expf(m2 - mn2);
        m1 = mn1; m2 = mn2;

        uint32_t p0[8], p1[8];
        float rs1 = 0.f, rs2 = 0.f;
        #pragma unroll
        for (int nc = 0; nc < 8; nc++) {
            __half h0 = __float2half_rn(__expf(s[nc][0] - mn1));
            __half h1 = __float2half_rn(__expf(s[nc][1] - mn1));
            __half h2 = __float2half_rn(__expf(s[nc][2] - mn2));
            __half h3 = __float2half_rn(__expf(s[nc][3] - mn2));
            p0[nc] = packh(h0, h1);
            p1[nc] = packh(h2, h3);
            rs1 += __half2float(h0) + __half2float(h1);
            rs2 += __half2float(h2) + __half2float(h3);
        }
        rs1 += __shfl_xor_sync(0xffffffffu, rs1, 1);
        rs1 += __shfl_xor_sync(0xffffffffu, rs1, 2);
        rs2 += __shfl_xor_sync(0xffffffffu, rs2, 1);
        rs2 += __shfl_xor_sync(0xffffffffu, rs2, 2);
        l1 = l1 * c1 + rs1;
        l2 = l2 * c2 + rs2;
        #pragma unroll
        for (int nc = 0; nc < 8; nc++) {
            o[nc][0] *= c1; o[nc][1] *= c1;
            o[nc][2] *= c2; o[nc][3] *= c2;
        }

        #pragma unroll
        for (int kc = 0; kc < 4; kc++) {
            uint32_t a[4] = { p0[2 * kc], p1[2 * kc], p0[2 * kc + 1], p1[2 * kc + 1] };
            #pragma unroll
            for (int np = 0; np < 4; np++) {
                uint32_t r0, r1, r2, r3;
                uint32_t addr = cVu + (uint32_t)((kc * 16 * PH + np * 16) * 2) + ldmoff;
                ldmx4t(r0, r1, r2, r3, addr);
                mma16(o[2 * np],     a, r0, r1);
                mma16(o[2 * np + 1], a, r2, r3);
            }
        }

        __syncthreads();
        buf ^= 1;
    }

    const float i1 = 1.f / l1, i2 = 1.f / l2;
    const int r0 = qrow0 + w * 16 + g;
    #pragma unroll
    for (int nc = 0; nc < 8; nc++) {
        int col = coff + nc * 8 + 2 * t;
        float2 x0 = *(const float2*)(X + (size_t)r0 * ED + col);
        float2 x1 = *(const float2*)(X + (size_t)(r0 + 8) * ED + col);
        *(uint32_t*)(CH + (size_t)r0 * ED + col) =
            packh(__float2half_rn(o[nc][0] * i1 + x0.x),
                  __float2half_rn(o[nc][1] * i1 + x0.y));
        *(uint32_t*)(CH + (size_t)(r0 + 8) * ED + col) =
            packh(__float2half_rn(o[nc][2] * i2 + x1.x),
                  __float2half_rn(o[nc][3] * i2 + x1.y));
    }
}

// ---------------------------------------------------------------------------
extern "C" void kernel_launch(void* const* d_in, const int* in_sizes, int n_in,
                              void* d_out, int out_size)
{
    const float* x  = (const float*)d_in[0];
    const float* wq = (const float*)d_in[1];
    const float* bq = (const float*)d_in[2];
    const float* wk = (const float*)d_in[3];
    const float* bk = (const float*)d_in[4];
    const float* wv = (const float*)d_in[5];
    const float* bv = (const float*)d_in[6];
    const float* wo = (const float*)d_in[7];
    const float* bo = (const float*)d_in[8];
    float* out = (float*)d_out;

    __half *Qh, *Kh, *Vh, *xh, *ch, *wh;
    cudaGetSymbolAddress((void**)&Qh, g_Qh);
    cudaGetSymbolAddress((void**)&Kh, g_Kh);
    cudaGetSymbolAddress((void**)&Vh, g_Vh);
    cudaGetSymbolAddress((void**)&xh, g_xh);
    cudaGetSymbolAddress((void**)&ch, g_ch);
    cudaGetSymbolAddress((void**)&wh, g_wh);

    // round inputs to fp16
    around<<<MTOT * ED / 1024, 256>>>(x, xh);
    dim3 wgrid(ED / 32, ED / 32), wblk(32, 8);
    wround<<<wgrid, wblk>>>(wq, wh + 0 * (size_t)ED * ED);
    wround<<<wgrid, wblk>>>(wk, wh + 1 * (size_t)ED * ED);
    wround<<<wgrid, wblk>>>(wv, wh + 2 * (size_t)ED * ED);
    wround<<<wgrid, wblk>>>(wo, wh + 3 * (size_t)ED * ED);

    // fused QKV projection (Q pre-scaled by 0.125)
    gemm_qkv<<<dim3(3 * ED / 128, MTOT / 128), 256>>>(xh, wh, bq, bk, bv, Qh, Kh, Vh);

    // attention + residual -> ctx (fp16)
    attn_h<<<dim3(SEQ / 128, NH, BATCH), 256>>>(Qh, Kh, Vh, x, ch);

    // output projection (fp32 out)
    gemm_o<<<dim3(ED / 128, MTOT / 128), 256>>>(ch, wh + 3 * (size_t)ED * ED, bo, out);
}

// round 8
// speedup vs baseline: 8.7195x; 1.0318x over previous
#include <cuda_runtime.h>
#include <cuda_fp16.h>
#include <stdint.h>

#define ED   1024
#define NH   16
#define HD   64
#define SEQ  2048
#define BATCH 2
#define MTOT (BATCH*SEQ)

// scratch (__device__ globals: allocation-free rule)
__device__ __half g_Qh[MTOT * ED];
__device__ __half g_Kh[MTOT * ED];
__device__ __half g_Vh[MTOT * ED];
__device__ __half g_xh[MTOT * ED];
__device__ __half g_ch[MTOT * ED];
__device__ __half g_wh[4][ED * ED];        // K-major [N][K]; [0..2] packed QKV

// Q pre-scale: (1/sqrt(64)) * log2(e)  -> softmax in exp2 domain
#define QSCALE 0.1803368801111164f

// ---------------------------------------------------------------------------
// helpers
// ---------------------------------------------------------------------------
__device__ __forceinline__ uint32_t packh(__half a, __half b) {
    return (uint32_t)__half_as_ushort(a) | ((uint32_t)__half_as_ushort(b) << 16);
}
__device__ __forceinline__ void mma16(float* d, const uint32_t* a, uint32_t b0, uint32_t b1) {
    asm volatile(
        "mma.sync.aligned.m16n8k16.row.col.f32.f16.f16.f32 "
        "{%0,%1,%2,%3}, {%4,%5,%6,%7}, {%8,%9}, {%0,%1,%2,%3};\n"
        : "+f"(d[0]), "+f"(d[1]), "+f"(d[2]), "+f"(d[3])
        : "r"(a[0]), "r"(a[1]), "r"(a[2]), "r"(a[3]), "r"(b0), "r"(b1));
}
__device__ __forceinline__ void cpa16(void* sdst, const void* gsrc) {
    uint32_t sa = (uint32_t)__cvta_generic_to_shared(sdst);
    asm volatile("cp.async.cg.shared.global [%0], [%1], 16;\n" :: "r"(sa), "l"(gsrc));
}
#define CP_COMMIT() asm volatile("cp.async.commit_group;\n" ::: "memory")
#define CP_WAIT1()  asm volatile("cp.async.wait_group 1;\n" ::: "memory")
#define CP_WAIT0()  asm volatile("cp.async.wait_group 0;\n" ::: "memory")

__device__ __forceinline__ void ldmx4t(uint32_t& r0, uint32_t& r1, uint32_t& r2,
                                       uint32_t& r3, uint32_t saddr) {
    asm volatile("ldmatrix.sync.aligned.m8n8.x4.trans.shared.b16 {%0,%1,%2,%3}, [%4];"
                 : "=r"(r0), "=r"(r1), "=r"(r2), "=r"(r3) : "r"(saddr));
}

// ---------------------------------------------------------------------------
// rounding kernels (fp32 -> fp16 RNE)
// ---------------------------------------------------------------------------
__global__ void __launch_bounds__(256)
around(const float* __restrict__ A, __half* __restrict__ oh)
{
    int i = blockIdx.x * 256 + threadIdx.x;
    float4 v = ((const float4*)A)[i];
    ((uint2*)oh)[i] = make_uint2(packh(__float2half_rn(v.x), __float2half_rn(v.y)),
                                 packh(__float2half_rn(v.z), __float2half_rn(v.w)));
}
// all 4 weights in one launch: z selects W; [K][N] fp32 -> K-major [N][K] fp16
__global__ void __launch_bounds__(256)
wround4(const float* __restrict__ W0, const float* __restrict__ W1,
        const float* __restrict__ W2, const float* __restrict__ W3,
        __half* __restrict__ bhBase)
{
    __shared__ float t[32][33];
    const float* W = (blockIdx.z == 0) ? W0 : (blockIdx.z == 1) ? W1
                   : (blockIdx.z == 2) ? W2 : W3;
    __half* bh = bhBase + (size_t)blockIdx.z * ED * ED;
    int k0 = blockIdx.x * 32, n0 = blockIdx.y * 32;
    int tx = threadIdx.x, ty = threadIdx.y;            // (32, 8)
    #pragma unroll
    for (int i = 0; i < 4; i++)
        t[ty + 8 * i][tx] = W[(size_t)(k0 + ty + 8 * i) * ED + n0 + tx];
    __syncthreads();
    #pragma unroll
    for (int i = 0; i < 4; i++)
        bh[(size_t)(n0 + ty + 8 * i) * ED + k0 + tx] = __float2half_rn(t[tx][ty + 8 * i]);
}

// ---------------------------------------------------------------------------
// fp16 GEMM mainloop: 128x128 tile, k-chunk 32, 8 warps (2x4), warp tile 64x32,
// cp.async double buffer. Pitch 40 halves (conflict-free frag LDS).
// ---------------------------------------------------------------------------
#define GP   40
#define GSTG (128 * GP)

#define GEMM_MAIN(A_, B_)                                                          \
    __shared__ __half hsm[2][2 * GSTG];                                            \
    const int tid = threadIdx.x;                                                   \
    const int w = tid >> 5, lane = tid & 31, g = lane >> 2, t = lane & 3;          \
    const int wm = w >> 2, wn = w & 3;                                             \
    const int m0 = blockIdx.y * 128;                                               \
    const int nrow0 = blockIdx.x * 128;                                            \
    float acc[4][4][4] = {};                                                       \
    auto stage = [&](int c, int s) {                                               \
        __half* base = hsm[s];                                                     \
        const int k0 = c * 32;                                                     \
        _Pragma("unroll")                                                          \
        for (int i = 0; i < 2; i++) {                                              \
            int id = i * 256 + tid;                                                \
            int r = id >> 2, c8 = (id & 3) << 3;                                   \
            cpa16(base + r * GP + c8,        A_ + (size_t)(m0 + r) * ED + k0 + c8);\
            cpa16(base + GSTG + r * GP + c8, B_ + (size_t)(nrow0 + r) * ED + k0 + c8);\
        }                                                                          \
        CP_COMMIT();                                                               \
    };                                                                             \
    stage(0, 0);                                                                   \
    int buf = 0;                                                                   \
    for (int c = 0; c < 32; c++) {                                                 \
        if (c + 1 < 32) { stage(c + 1, buf ^ 1); CP_WAIT1(); }                     \
        else            { CP_WAIT0(); }                                            \
        __syncthreads();                                                           \
        const __half* cA = hsm[buf];                                               \
        const __half* cB = cA + GSTG;                                              \
        _Pragma("unroll")                                                          \
        for (int ks = 0; ks < 2; ks++) {                                           \
            const int kc = ks * 16 + 2 * t;                                        \
            uint32_t af[4][4];                                                     \
            _Pragma("unroll")                                                      \
            for (int mt = 0; mt < 4; mt++) {                                       \
                int row = wm * 64 + mt * 16;                                       \
                af[mt][0] = *(const uint32_t*)(cA + (row + g    ) * GP + kc);      \
                af[mt][1] = *(const uint32_t*)(cA + (row + g + 8) * GP + kc);      \
                af[mt][2] = *(const uint32_t*)(cA + (row + g    ) * GP + kc + 8);  \
                af[mt][3] = *(const uint32_t*)(cA + (row + g + 8) * GP + kc + 8);  \
            }                                                                      \
            uint32_t bf[4][2];                                                     \
            _Pragma("unroll")                                                      \
            for (int nc = 0; nc < 4; nc++) {                                       \
                int col = wn * 32 + nc * 8 + g;                                    \
                bf[nc][0] = *(const uint32_t*)(cB + col * GP + kc);                \
                bf[nc][1] = *(const uint32_t*)(cB + col * GP + kc + 8);            \
            }                                                                      \
            _Pragma("unroll")                                                      \
            for (int mt = 0; mt < 4; mt++)                                         \
                _Pragma("unroll")                                                  \
                for (int nc = 0; nc < 4; nc++)                                     \
                    mma16(acc[mt][nc], af[mt], bf[nc][0], bf[nc][1]);              \
        }                                                                          \
        __syncthreads();                                                           \
        buf ^= 1;                                                                  \
    }

// fused QKV: B packed [3072][1024]; seg 0=Q (xQSCALE, exp2 domain), 1=K, 2=V
__global__ void __launch_bounds__(256, 2)
gemm_qkv(const __half* __restrict__ A, const __half* __restrict__ B,
         const float* __restrict__ bq, const float* __restrict__ bk,
         const float* __restrict__ bv,
         __half* __restrict__ Qh, __half* __restrict__ Kh, __half* __restrict__ Vh)
{
    GEMM_MAIN(A, B)

    const int seg = blockIdx.x >> 3;
    const int ncol0 = (blockIdx.x & 7) * 128;
    const float* bias = (seg == 0) ? bq : (seg == 1) ? bk : bv;
    __half* O = (seg == 0) ? Qh : (seg == 1) ? Kh : Vh;
    const float sc = (seg == 0) ? QSCALE : 1.0f;

    #pragma unroll
    for (int mt = 0; mt < 4; mt++) {
        int row = m0 + wm * 64 + mt * 16 + g;
        #pragma unroll
        for (int nc = 0; nc < 4; nc++) {
            int col = ncol0 + wn * 32 + nc * 8 + 2 * t;
            float b0 = bias[col], b1 = bias[col + 1];
            *(uint32_t*)(O + (size_t)row * ED + col) =
                packh(__float2half_rn((acc[mt][nc][0] + b0) * sc),
                      __float2half_rn((acc[mt][nc][1] + b1) * sc));
            *(uint32_t*)(O + (size_t)(row + 8) * ED + col) =
                packh(__float2half_rn((acc[mt][nc][2] + b0) * sc),
                      __float2half_rn((acc[mt][nc][3] + b1) * sc));
        }
    }
}

// O projection: float out
__global__ void __launch_bounds__(256, 2)
gemm_o(const __half* __restrict__ A, const __half* __restrict__ B,
       const float* __restrict__ bias, float* __restrict__ out)
{
    GEMM_MAIN(A, B)

    #pragma unroll
    for (int mt = 0; mt < 4; mt++) {
        int row = m0 + wm * 64 + mt * 16 + g;
        #pragma unroll
        for (int nc = 0; nc < 4; nc++) {
            int col = nrow0 + wn * 32 + nc * 8 + 2 * t;
            float b0 = bias[col], b1 = bias[col + 1];
            *(float2*)(out + (size_t)row * ED + col) =
                make_float2(acc[mt][nc][0] + b0, acc[mt][nc][1] + b1);
            *(float2*)(out + (size_t)(row + 8) * ED + col) =
                make_float2(acc[mt][nc][2] + b0, acc[mt][nc][3] + b1);
        }
    }
}

// ---------------------------------------------------------------------------
// fp16 flash attention, exp2 domain, 2 CTAs/SM. 256 thr, 128-q tile.
// ---------------------------------------------------------------------------
#define PH   72
#define HSTG (64 * PH)

__global__ void __launch_bounds__(256, 2)
attn_h(const __half* __restrict__ Q, const __half* __restrict__ K,
       const __half* __restrict__ V, const float* __restrict__ X,
       __half* __restrict__ CH)
{
    __shared__ __half hsm[4 * HSTG];        // 36864 B
    __half* sK = hsm;
    __half* sV = hsm + 2 * HSTG;

    const int tid = threadIdx.x;
    const int w = tid >> 5, lane = tid & 31, g = lane >> 2, t = lane & 3;
    const int qt = blockIdx.x, h = blockIdx.y, b = blockIdx.z;
    const int qrow0 = b * SEQ + qt * 128;
    const int coff  = h * HD;

    const int matq = lane >> 3;
    const uint32_t ldmoff = (uint32_t)((((matq & 1) * 8 + (lane & 7)) * PH +
                                        (matq >> 1) * 8) * 2);
    const uint32_t sVu = (uint32_t)__cvta_generic_to_shared(sV);

    uint32_t qf[4][4];
    {
        const int r0 = qrow0 + w * 16 + g;
        #pragma unroll
        for (int kc = 0; kc < 4; kc++) {
            int c0 = coff + kc * 16 + 2 * t;
            qf[kc][0] = *(const uint32_t*)(Q + (size_t)r0 * ED + c0);
            qf[kc][1] = *(const uint32_t*)(Q + (size_t)(r0 + 8) * ED + c0);
            qf[kc][2] = *(const uint32_t*)(Q + (size_t)r0 * ED + c0 + 8);
            qf[kc][3] = *(const uint32_t*)(Q + (size_t)(r0 + 8) * ED + c0 + 8);
        }
    }

    auto stage = [&](int kt, int s) {
        const int krow0 = b * SEQ + kt * 64;
        __half* dK = sK + s * HSTG;
        __half* dV = sV + s * HSTG;
        #pragma unroll
        for (int i = 0; i < 2; i++) {
            int id = i * 256 + tid;
            int r = id >> 3, c8 = (id & 7) << 3;
            cpa16(dK + r * PH + c8, K + (size_t)(krow0 + r) * ED + coff + c8);
            cpa16(dV + r * PH + c8, V + (size_t)(krow0 + r) * ED + coff + c8);
        }
        CP_COMMIT();
    };

    stage(0, 0);

    float m1 = -1e30f, m2 = -1e30f, l1 = 0.f, l2 = 0.f;
    float o[8][4] = {};

    int buf = 0;
    for (int kt = 0; kt < SEQ / 64; kt++) {
        if (kt + 1 < SEQ / 64) { stage(kt + 1, buf ^ 1); CP_WAIT1(); }
        else                   { CP_WAIT0(); }
        __syncthreads();

        const __half* cK = sK + buf * HSTG;
        const uint32_t cVu = sVu + (uint32_t)(buf * HSTG * 2);

        // S = Q @ K^T  (log2 domain — Q carries 0.125*log2e)
        float s[8][4] = {};
        #pragma unroll
        for (int kc = 0; kc < 4; kc++) {
            const int kcc = kc * 16 + 2 * t;
            #pragma unroll
            for (int nc = 0; nc < 8; nc++) {
                uint32_t b0 = *(const uint32_t*)(cK + (nc * 8 + g) * PH + kcc);
                uint32_t b1 = *(const uint32_t*)(cK + (nc * 8 + g) * PH + kcc + 8);
                mma16(s[nc], qf[kc], b0, b1);
            }
        }

        // online softmax in exp2 domain (rows g, g+8; quad reduce)
        float tm1 = -1e30f, tm2 = -1e30f;
        #pragma unroll
        for (int nc = 0; nc < 8; nc++) {
            tm1 = fmaxf(tm1, fmaxf(s[nc][0], s[nc][1]));
            tm2 = fmaxf(tm2, fmaxf(s[nc][2], s[nc][3]));
        }
        tm1 = fmaxf(tm1, __shfl_xor_sync(0xffffffffu, tm1, 1));
        tm1 = fmaxf(tm1, __shfl_xor_sync(0xffffffffu, tm1, 2));
        tm2 = fmaxf(tm2, __shfl_xor_sync(0xffffffffu, tm2, 1));
        tm2 = fmaxf(tm2, __shfl_xor_sync(0xffffffffu, tm2, 2));

        float mn1 = fmaxf(m1, tm1), mn2 = fmaxf(m2, tm2);
        float c1 = exp2f(m1 - mn1), c2 = exp2f(m2 - mn2);
        m1 = mn1; m2 = mn2;

        uint32_t p0[8], p1[8];
        float rs1 = 0.f, rs2 = 0.f;
        #pragma unroll
        for (int nc = 0; nc < 8; nc++) {
            __half h0 = __float2half_rn(exp2f(s[nc][0] - mn1));
            __half h1 = __float2half_rn(exp2f(s[nc][1] - mn1));
            __half h2 = __float2half_rn(exp2f(s[nc][2] - mn2));
            __half h3 = __float2half_rn(exp2f(s[nc][3] - mn2));
            p0[nc] = packh(h0, h1);
            p1[nc] = packh(h2, h3);
            rs1 += __half2float(h0) + __half2float(h1);
            rs2 += __half2float(h2) + __half2float(h3);
        }
        rs1 += __shfl_xor_sync(0xffffffffu, rs1, 1);
        rs1 += __shfl_xor_sync(0xffffffffu, rs1, 2);
        rs2 += __shfl_xor_sync(0xffffffffu, rs2, 1);
        rs2 += __shfl_xor_sync(0xffffffffu, rs2, 2);
        l1 = l1 * c1 + rs1;
        l2 = l2 * c2 + rs2;
        #pragma unroll
        for (int nc = 0; nc < 8; nc++) {
            o[nc][0] *= c1; o[nc][1] *= c1;
            o[nc][2] *= c2; o[nc][3] *= c2;
        }

        // O += P @ V
        #pragma unroll
        for (int kc = 0; kc < 4; kc++) {
            uint32_t a[4] = { p0[2 * kc], p1[2 * kc], p0[2 * kc + 1], p1[2 * kc + 1] };
            #pragma unroll
            for (int np = 0; np < 4; np++) {
                uint32_t r0, r1, r2, r3;
                uint32_t addr = cVu + (uint32_t)((kc * 16 * PH + np * 16) * 2) + ldmoff;
                ldmx4t(r0, r1, r2, r3, addr);
                mma16(o[2 * np],     a, r0, r1);
                mma16(o[2 * np + 1], a, r2, r3);
            }
        }

        __syncthreads();
        buf ^= 1;
    }

    const float i1 = 1.f / l1, i2 = 1.f / l2;
    const int r0 = qrow0 + w * 16 + g;
    #pragma unroll
    for (int nc = 0; nc < 8; nc++) {
        int col = coff + nc * 8 + 2 * t;
        float2 x0 = *(const float2*)(X + (size_t)r0 * ED + col);
        float2 x1 = *(const float2*)(X + (size_t)(r0 + 8) * ED + col);
        *(uint32_t*)(CH + (size_t)r0 * ED + col) =
            packh(__float2half_rn(o[nc][0] * i1 + x0.x),
                  __float2half_rn(o[nc][1] * i1 + x0.y));
        *(uint32_t*)(CH + (size_t)(r0 + 8) * ED + col) =
            packh(__float2half_rn(o[nc][2] * i2 + x1.x),
                  __float2half_rn(o[nc][3] * i2 + x1.y));
    }
}

// ---------------------------------------------------------------------------
extern "C" void kernel_launch(void* const* d_in, const int* in_sizes, int n_in,
                              void* d_out, int out_size)
{
    const float* x  = (const float*)d_in[0];
    const float* wq = (const float*)d_in[1];
    const float* bq = (const float*)d_in[2];
    const float* wk = (const float*)d_in[3];
    const float* bk = (const float*)d_in[4];
    const float* wv = (const float*)d_in[5];
    const float* bv = (const float*)d_in[6];
    const float* wo = (const float*)d_in[7];
    const float* bo = (const float*)d_in[8];
    float* out = (float*)d_out;

    __half *Qh, *Kh, *Vh, *xh, *ch, *wh;
    cudaGetSymbolAddress((void**)&Qh, g_Qh);
    cudaGetSymbolAddress((void**)&Kh, g_Kh);
    cudaGetSymbolAddress((void**)&Vh, g_Vh);
    cudaGetSymbolAddress((void**)&xh, g_xh);
    cudaGetSymbolAddress((void**)&ch, g_ch);
    cudaGetSymbolAddress((void**)&wh, g_wh);

    // round inputs to fp16 (weights: single fused launch)
    around<<<MTOT * ED / 1024, 256>>>(x, xh);
    wround4<<<dim3(ED / 32, ED / 32, 4), dim3(32, 8)>>>(wq, wk, wv, wo, wh);

    // fused QKV projection (Q in exp2 domain)
    gemm_qkv<<<dim3(3 * ED / 128, MTOT / 128), 256>>>(xh, wh, bq, bk, bv, Qh, Kh, Vh);

    // attention + residual -> ctx (fp16)
    attn_h<<<dim3(SEQ / 128, NH, BATCH), 256>>>(Qh, Kh, Vh, x, ch);

    // output projection (fp32 out)
    gemm_o<<<dim3(ED / 128, MTOT / 128), 256>>>(ch, wh + 3 * (size_t)ED * ED, bo, out);
}

// round 9
// speedup vs baseline: 9.4160x; 1.0799x over previous
#include <cuda_runtime.h>
#include <cuda_fp16.h>
#include <stdint.h>

#define ED   1024
#define NH   16
#define HD   64
#define SEQ  2048
#define BATCH 2
#define MTOT (BATCH*SEQ)

// scratch (__device__ globals: allocation-free rule)
__device__ __half g_Qh[MTOT * ED];
__device__ __half g_Kh[MTOT * ED];
__device__ __half g_Vh[MTOT * ED];
__device__ __half g_xh[MTOT * ED];
__device__ __half g_ch[MTOT * ED];
__device__ __half g_wh[4][ED * ED];        // K-major [N][K]; [0..2] packed QKV

// Q pre-scale: (1/sqrt(64)) * log2(e)  -> softmax in exp2 domain
#define QSCALE 0.1803368801111164f

// ---------------------------------------------------------------------------
// helpers
// ---------------------------------------------------------------------------
__device__ __forceinline__ uint32_t packh(__half a, __half b) {
    return (uint32_t)__half_as_ushort(a) | ((uint32_t)__half_as_ushort(b) << 16);
}
__device__ __forceinline__ void mma16(float* d, const uint32_t* a, uint32_t b0, uint32_t b1) {
    asm volatile(
        "mma.sync.aligned.m16n8k16.row.col.f32.f16.f16.f32 "
        "{%0,%1,%2,%3}, {%4,%5,%6,%7}, {%8,%9}, {%0,%1,%2,%3};\n"
        : "+f"(d[0]), "+f"(d[1]), "+f"(d[2]), "+f"(d[3])
        : "r"(a[0]), "r"(a[1]), "r"(a[2]), "r"(a[3]), "r"(b0), "r"(b1));
}
__device__ __forceinline__ void cpa16(void* sdst, const void* gsrc) {
    uint32_t sa = (uint32_t)__cvta_generic_to_shared(sdst);
    asm volatile("cp.async.cg.shared.global [%0], [%1], 16;\n" :: "r"(sa), "l"(gsrc));
}
#define CP_COMMIT() asm volatile("cp.async.commit_group;\n" ::: "memory")
#define CP_WAIT1()  asm volatile("cp.async.wait_group 1;\n" ::: "memory")
#define CP_WAIT0()  asm volatile("cp.async.wait_group 0;\n" ::: "memory")

__device__ __forceinline__ void ldmx4(uint32_t& r0, uint32_t& r1, uint32_t& r2,
                                      uint32_t& r3, uint32_t saddr) {
    asm volatile("ldmatrix.sync.aligned.m8n8.x4.shared.b16 {%0,%1,%2,%3}, [%4];"
                 : "=r"(r0), "=r"(r1), "=r"(r2), "=r"(r3) : "r"(saddr));
}
__device__ __forceinline__ void ldmx4t(uint32_t& r0, uint32_t& r1, uint32_t& r2,
                                       uint32_t& r3, uint32_t saddr) {
    asm volatile("ldmatrix.sync.aligned.m8n8.x4.trans.shared.b16 {%0,%1,%2,%3}, [%4];"
                 : "=r"(r0), "=r"(r1), "=r"(r2), "=r"(r3) : "r"(saddr));
}

// ---------------------------------------------------------------------------
// rounding kernels (fp32 -> fp16 RNE)
// ---------------------------------------------------------------------------
__global__ void __launch_bounds__(256)
around(const float* __restrict__ A, __half* __restrict__ oh)
{
    int i = blockIdx.x * 256 + threadIdx.x;
    float4 v = ((const float4*)A)[i];
    ((uint2*)oh)[i] = make_uint2(packh(__float2half_rn(v.x), __float2half_rn(v.y)),
                                 packh(__float2half_rn(v.z), __float2half_rn(v.w)));
}
__global__ void __launch_bounds__(256)
wround4(const float* __restrict__ W0, const float* __restrict__ W1,
        const float* __restrict__ W2, const float* __restrict__ W3,
        __half* __restrict__ bhBase)
{
    __shared__ float t[32][33];
    const float* W = (blockIdx.z == 0) ? W0 : (blockIdx.z == 1) ? W1
                   : (blockIdx.z == 2) ? W2 : W3;
    __half* bh = bhBase + (size_t)blockIdx.z * ED * ED;
    int k0 = blockIdx.x * 32, n0 = blockIdx.y * 32;
    int tx = threadIdx.x, ty = threadIdx.y;            // (32, 8)
    #pragma unroll
    for (int i = 0; i < 4; i++)
        t[ty + 8 * i][tx] = W[(size_t)(k0 + ty + 8 * i) * ED + n0 + tx];
    __syncthreads();
    #pragma unroll
    for (int i = 0; i < 4; i++)
        bh[(size_t)(n0 + ty + 8 * i) * ED + k0 + tx] = __float2half_rn(t[tx][ty + 8 * i]);
}

// ---------------------------------------------------------------------------
// fp16 GEMM mainloop: 128x128 tile, k-chunk 32, 8 warps (2x4), warp tile 64x32.
// cp.async double buffer, ldmatrix.x4 fragment loads. Pitch 40 halves.
// ---------------------------------------------------------------------------
#define GP   40
#define GSTG (128 * GP)

#define GEMM_MAIN(A_, B_)                                                          \
    __shared__ __half hsm[2][2 * GSTG];                                            \
    const int tid = threadIdx.x;                                                   \
    const int w = tid >> 5, lane = tid & 31, g = lane >> 2, t = lane & 3;          \
    const int wm = w >> 2, wn = w & 3;                                             \
    const int m0 = blockIdx.y * 128;                                               \
    const int nrow0 = blockIdx.x * 128;                                            \
    const uint32_t hsmu = (uint32_t)__cvta_generic_to_shared(hsm);                 \
    /* ldmatrix per-lane offsets (bytes) */                                        \
    const uint32_t aoff = (uint32_t)(((lane & 15) * GP + (lane >> 4) * 8) * 2);    \
    const uint32_t boff = (uint32_t)((((lane & 7) + ((lane >> 4) << 3)) * GP +     \
                                      (((lane >> 3) & 1) * 8)) * 2);               \
    float acc[4][4][4] = {};                                                       \
    auto stage = [&](int c, int s) {                                               \
        __half* base = hsm[s];                                                     \
        const int k0 = c * 32;                                                     \
        _Pragma("unroll")                                                          \
        for (int i = 0; i < 2; i++) {                                              \
            int id = i * 256 + tid;                                                \
            int r = id >> 2, c8 = (id & 3) << 3;                                   \
            cpa16(base + r * GP + c8,        A_ + (size_t)(m0 + r) * ED + k0 + c8);\
            cpa16(base + GSTG + r * GP + c8, B_ + (size_t)(nrow0 + r) * ED + k0 + c8);\
        }                                                                          \
        CP_COMMIT();                                                               \
    };                                                                             \
    stage(0, 0);                                                                   \
    int buf = 0;                                                                   \
    for (int c = 0; c < 32; c++) {                                                 \
        if (c + 1 < 32) { stage(c + 1, buf ^ 1); CP_WAIT1(); }                     \
        else            { CP_WAIT0(); }                                            \
        __syncthreads();                                                           \
        const uint32_t cAu = hsmu + (uint32_t)(buf * 4 * GSTG);                    \
        const uint32_t cBu = cAu + (uint32_t)(2 * GSTG);                           \
        _Pragma("unroll")                                                          \
        for (int ks = 0; ks < 2; ks++) {                                           \
            uint32_t af[4][4];                                                     \
            _Pragma("unroll")                                                      \
            for (int mt = 0; mt < 4; mt++)                                         \
                ldmx4(af[mt][0], af[mt][1], af[mt][2], af[mt][3],                  \
                      cAu + (uint32_t)((((wm * 64 + mt * 16) * GP) + ks * 16) * 2) \
                          + aoff);                                                 \
            uint32_t bf[4][2];                                                     \
            _Pragma("unroll")                                                      \
            for (int np = 0; np < 2; np++)                                         \
                ldmx4(bf[2 * np][0], bf[2 * np][1], bf[2 * np + 1][0],             \
                      bf[2 * np + 1][1],                                           \
                      cBu + (uint32_t)((((wn * 32 + np * 16) * GP) + ks * 16) * 2) \
                          + boff);                                                 \
            _Pragma("unroll")                                                      \
            for (int mt = 0; mt < 4; mt++)                                         \
                _Pragma("unroll")                                                  \
                for (int nc = 0; nc < 4; nc++)                                     \
                    mma16(acc[mt][nc], af[mt], bf[nc][0], bf[nc][1]);              \
        }                                                                          \
        __syncthreads();                                                           \
        buf ^= 1;                                                                  \
    }

// fused QKV: B packed [3072][1024]; seg 0=Q (xQSCALE, exp2 domain), 1=K, 2=V
__global__ void __launch_bounds__(256, 2)
gemm_qkv(const __half* __restrict__ A, const __half* __restrict__ B,
         const float* __restrict__ bq, const float* __restrict__ bk,
         const float* __restrict__ bv,
         __half* __restrict__ Qh, __half* __restrict__ Kh, __half* __restrict__ Vh)
{
    GEMM_MAIN(A, B)

    const int seg = blockIdx.x >> 3;
    const int ncol0 = (blockIdx.x & 7) * 128;
    const float* bias = (seg == 0) ? bq : (seg == 1) ? bk : bv;
    __half* O = (seg == 0) ? Qh : (seg == 1) ? Kh : Vh;
    const float sc = (seg == 0) ? QSCALE : 1.0f;

    #pragma unroll
    for (int mt = 0; mt < 4; mt++) {
        int row = m0 + wm * 64 + mt * 16 + g;
        #pragma unroll
        for (int nc = 0; nc < 4; nc++) {
            int col = ncol0 + wn * 32 + nc * 8 + 2 * t;
            float b0 = bias[col], b1 = bias[col + 1];
            *(uint32_t*)(O + (size_t)row * ED + col) =
                packh(__float2half_rn((acc[mt][nc][0] + b0) * sc),
                      __float2half_rn((acc[mt][nc][1] + b1) * sc));
            *(uint32_t*)(O + (size_t)(row + 8) * ED + col) =
                packh(__float2half_rn((acc[mt][nc][2] + b0) * sc),
                      __float2half_rn((acc[mt][nc][3] + b1) * sc));
        }
    }
}

// O projection: float out
__global__ void __launch_bounds__(256, 2)
gemm_o(const __half* __restrict__ A, const __half* __restrict__ B,
       const float* __restrict__ bias, float* __restrict__ out)
{
    GEMM_MAIN(A, B)

    #pragma unroll
    for (int mt = 0; mt < 4; mt++) {
        int row = m0 + wm * 64 + mt * 16 + g;
        #pragma unroll
        for (int nc = 0; nc < 4; nc++) {
            int col = nrow0 + wn * 32 + nc * 8 + 2 * t;
            float b0 = bias[col], b1 = bias[col + 1];
            *(float2*)(out + (size_t)row * ED + col) =
                make_float2(acc[mt][nc][0] + b0, acc[mt][nc][1] + b1);
            *(float2*)(out + (size_t)(row + 8) * ED + col) =
                make_float2(acc[mt][nc][2] + b0, acc[mt][nc][3] + b1);
        }
    }
}

// ---------------------------------------------------------------------------
// fp16 flash attention, exp2 domain, 2 CTAs/SM, ldmatrix fragment loads.
// ---------------------------------------------------------------------------
#define PH   72
#define HSTG (64 * PH)

__global__ void __launch_bounds__(256, 2)
attn_h(const __half* __restrict__ Q, const __half* __restrict__ K,
       const __half* __restrict__ V, const float* __restrict__ X,
       __half* __restrict__ CH)
{
    __shared__ __half hsm[4 * HSTG];        // 36864 B
    __half* sK = hsm;
    __half* sV = hsm + 2 * HSTG;

    const int tid = threadIdx.x;
    const int w = tid >> 5, lane = tid & 31, g = lane >> 2, t = lane & 3;
    const int qt = blockIdx.x, h = blockIdx.y, b = blockIdx.z;
    const int qrow0 = b * SEQ + qt * 128;
    const int coff  = h * HD;

    // ldmatrix per-lane offsets (bytes)
    const int matq = lane >> 3;
    const uint32_t ldmoffV = (uint32_t)((((matq & 1) * 8 + (lane & 7)) * PH +
                                         (matq >> 1) * 8) * 2);          // V (trans)
    const uint32_t ldmoffK = (uint32_t)((((lane & 7) + ((lane >> 4) << 3)) * PH +
                                         (((lane >> 3) & 1) * 8)) * 2);  // K (B-frag)
    const uint32_t sKu = (uint32_t)__cvta_generic_to_shared(sK);
    const uint32_t sVu = (uint32_t)__cvta_generic_to_shared(sV);

    uint32_t qf[4][4];
    {
        const int r0 = qrow0 + w * 16 + g;
        #pragma unroll
        for (int kc = 0; kc < 4; kc++) {
            int c0 = coff + kc * 16 + 2 * t;
            qf[kc][0] = *(const uint32_t*)(Q + (size_t)r0 * ED + c0);
            qf[kc][1] = *(const uint32_t*)(Q + (size_t)(r0 + 8) * ED + c0);
            qf[kc][2] = *(const uint32_t*)(Q + (size_t)r0 * ED + c0 + 8);
            qf[kc][3] = *(const uint32_t*)(Q + (size_t)(r0 + 8) * ED + c0 + 8);
        }
    }

    auto stage = [&](int kt, int s) {
        const int krow0 = b * SEQ + kt * 64;
        __half* dK = sK + s * HSTG;
        __half* dV = sV + s * HSTG;
        #pragma unroll
        for (int i = 0; i < 2; i++) {
            int id = i * 256 + tid;
            int r = id >> 3, c8 = (id & 7) << 3;
            cpa16(dK + r * PH + c8, K + (size_t)(krow0 + r) * ED + coff + c8);
            cpa16(dV + r * PH + c8, V + (size_t)(krow0 + r) * ED + coff + c8);
        }
        CP_COMMIT();
    };

    stage(0, 0);

    float m1 = -1e30f, m2 = -1e30f, l1 = 0.f, l2 = 0.f;
    float o[8][4] = {};

    int buf = 0;
    for (int kt = 0; kt < SEQ / 64; kt++) {
        if (kt + 1 < SEQ / 64) { stage(kt + 1, buf ^ 1); CP_WAIT1(); }
        else                   { CP_WAIT0(); }
        __syncthreads();

        const uint32_t cKu = sKu + (uint32_t)(buf * HSTG * 2);
        const uint32_t cVu = sVu + (uint32_t)(buf * HSTG * 2);

        // S = Q @ K^T  (K B-frags via ldmatrix.x4: 2 nc per instruction)
        float s[8][4] = {};
        #pragma unroll
        for (int kc = 0; kc < 4; kc++) {
            #pragma unroll
            for (int np = 0; np < 4; np++) {
                uint32_t b00, b01, b10, b11;
                ldmx4(b00, b01, b10, b11,
                      cKu + (uint32_t)((np * 16 * PH + kc * 16) * 2) + ldmoffK);
                mma16(s[2 * np],     qf[kc], b00, b01);
                mma16(s[2 * np + 1], qf[kc], b10, b11);
            }
        }

        // online softmax in exp2 domain (rows g, g+8; quad reduce)
        float tm1 = -1e30f, tm2 = -1e30f;
        #pragma unroll
        for (int nc = 0; nc < 8; nc++) {
            tm1 = fmaxf(tm1, fmaxf(s[nc][0], s[nc][1]));
            tm2 = fmaxf(tm2, fmaxf(s[nc][2], s[nc][3]));
        }
        tm1 = fmaxf(tm1, __shfl_xor_sync(0xffffffffu, tm1, 1));
        tm1 = fmaxf(tm1, __shfl_xor_sync(0xffffffffu, tm1, 2));
        tm2 = fmaxf(tm2, __shfl_xor_sync(0xffffffffu, tm2, 1));
        tm2 = fmaxf(tm2, __shfl_xor_sync(0xffffffffu, tm2, 2));

        float mn1 = fmaxf(m1, tm1), mn2 = fmaxf(m2, tm2);
        float c1 = exp2f(m1 - mn1), c2 = exp2f(m2 - mn2);
        m1 = mn1; m2 = mn2;

        uint32_t p0[8], p1[8];
        float rs1 = 0.f, rs2 = 0.f;
        #pragma unroll
        for (int nc = 0; nc < 8; nc++) {
            __half2 h01 = __float22half2_rn(make_float2(exp2f(s[nc][0] - mn1),
                                                        exp2f(s[nc][1] - mn1)));
            __half2 h23 = __float22half2_rn(make_float2(exp2f(s[nc][2] - mn2),
                                                        exp2f(s[nc][3] - mn2)));
            p0[nc] = *(uint32_t*)&h01;
            p1[nc] = *(uint32_t*)&h23;
            float2 f01 = __half22float2(h01), f23 = __half22float2(h23);
            rs1 += f01.x + f01.y;
            rs2 += f23.x + f23.y;
        }
        rs1 += __shfl_xor_sync(0xffffffffu, rs1, 1);
        rs1 += __shfl_xor_sync(0xffffffffu, rs1, 2);
        rs2 += __shfl_xor_sync(0xffffffffu, rs2, 1);
        rs2 += __shfl_xor_sync(0xffffffffu, rs2, 2);
        l1 = l1 * c1 + rs1;
        l2 = l2 * c2 + rs2;
        #pragma unroll
        for (int nc = 0; nc < 8; nc++) {
            o[nc][0] *= c1; o[nc][1] *= c1;
            o[nc][2] *= c2; o[nc][3] *= c2;
        }

        // O += P @ V  (V via ldmatrix.x4.trans)
        #pragma unroll
        for (int kc = 0; kc < 4; kc++) {
            uint32_t a[4] = { p0[2 * kc], p1[2 * kc], p0[2 * kc + 1], p1[2 * kc + 1] };
            #pragma unroll
            for (int np = 0; np < 4; np++) {
                uint32_t r0, r1, r2, r3;
                ldmx4t(r0, r1, r2, r3,
                       cVu + (uint32_t)((kc * 16 * PH + np * 16) * 2) + ldmoffV);
                mma16(o[2 * np],     a, r0, r1);
                mma16(o[2 * np + 1], a, r2, r3);
            }
        }

        __syncthreads();
        buf ^= 1;
    }

    const float i1 = 1.f / l1, i2 = 1.f / l2;
    const int r0 = qrow0 + w * 16 + g;
    #pragma unroll
    for (int nc = 0; nc < 8; nc++) {
        int col = coff + nc * 8 + 2 * t;
        float2 x0 = *(const float2*)(X + (size_t)r0 * ED + col);
        float2 x1 = *(const float2*)(X + (size_t)(r0 + 8) * ED + col);
        *(uint32_t*)(CH + (size_t)r0 * ED + col) =
            packh(__float2half_rn(o[nc][0] * i1 + x0.x),
                  __float2half_rn(o[nc][1] * i1 + x0.y));
        *(uint32_t*)(CH + (size_t)(r0 + 8) * ED + col) =
            packh(__float2half_rn(o[nc][2] * i2 + x1.x),
                  __float2half_rn(o[nc][3] * i2 + x1.y));
    }
}

// ---------------------------------------------------------------------------
extern "C" void kernel_launch(void* const* d_in, const int* in_sizes, int n_in,
                              void* d_out, int out_size)
{
    const float* x  = (const float*)d_in[0];
    const float* wq = (const float*)d_in[1];
    const float* bq = (const float*)d_in[2];
    const float* wk = (const float*)d_in[3];
    const float* bk = (const float*)d_in[4];
    const float* wv = (const float*)d_in[5];
    const float* bv = (const float*)d_in[6];
    const float* wo = (const float*)d_in[7];
    const float* bo = (const float*)d_in[8];
    float* out = (float*)d_out;

    __half *Qh, *Kh, *Vh, *xh, *ch, *wh;
    cudaGetSymbolAddress((void**)&Qh, g_Qh);
    cudaGetSymbolAddress((void**)&Kh, g_Kh);
    cudaGetSymbolAddress((void**)&Vh, g_Vh);
    cudaGetSymbolAddress((void**)&xh, g_xh);
    cudaGetSymbolAddress((void**)&ch, g_ch);
    cudaGetSymbolAddress((void**)&wh, g_wh);

    around<<<MTOT * ED / 1024, 256>>>(x, xh);
    wround4<<<dim3(ED / 32, ED / 32, 4), dim3(32, 8)>>>(wq, wk, wv, wo, wh);

    gemm_qkv<<<dim3(3 * ED / 128, MTOT / 128), 256>>>(xh, wh, bq, bk, bv, Qh, Kh, Vh);

    attn_h<<<dim3(SEQ / 128, NH, BATCH), 256>>>(Qh, Kh, Vh, x, ch);

    gemm_o<<<dim3(ED / 128, MTOT / 128), 256>>>(ch, wh + 3 * (size_t)ED * ED, bo, out);
}

// round 11
// speedup vs baseline: 10.2211x; 1.0855x over previous
#include <cuda_runtime.h>
#include <cuda_fp16.h>
#include <stdint.h>

#define ED   1024
#define NH   16
#define HD   64
#define SEQ  2048
#define BATCH 2
#define MTOT (BATCH*SEQ)

// scratch (__device__ globals: allocation-free rule)
__device__ __half g_Qh[MTOT * ED];
__device__ __half g_Kh[MTOT * ED];
__device__ __half g_Vh[MTOT * ED];
__device__ __half g_xh[MTOT * ED];
__device__ __half g_ch[MTOT * ED];
__device__ __half g_wh[4][ED * ED];        // K-major [N][K]; [0..2] packed QKV

// Q pre-scale: (1/sqrt(64)) * log2(e)  -> softmax in exp2 domain
#define QSCALE 0.1803368801111164f

// ---------------------------------------------------------------------------
// helpers
// ---------------------------------------------------------------------------
__device__ __forceinline__ uint32_t packh(__half a, __half b) {
    return (uint32_t)__half_as_ushort(a) | ((uint32_t)__half_as_ushort(b) << 16);
}
__device__ __forceinline__ void mma16(float* d, const uint32_t* a, uint32_t b0, uint32_t b1) {
    asm volatile(
        "mma.sync.aligned.m16n8k16.row.col.f32.f16.f16.f32 "
        "{%0,%1,%2,%3}, {%4,%5,%6,%7}, {%8,%9}, {%0,%1,%2,%3};\n"
        : "+f"(d[0]), "+f"(d[1]), "+f"(d[2]), "+f"(d[3])
        : "r"(a[0]), "r"(a[1]), "r"(a[2]), "r"(a[3]), "r"(b0), "r"(b1));
}
__device__ __forceinline__ void cpa16(void* sdst, const void* gsrc) {
    uint32_t sa = (uint32_t)__cvta_generic_to_shared(sdst);
    asm volatile("cp.async.cg.shared.global [%0], [%1], 16;\n" :: "r"(sa), "l"(gsrc));
}
#define CP_COMMIT() asm volatile("cp.async.commit_group;\n" ::: "memory")
#define CP_WAIT1()  asm volatile("cp.async.wait_group 1;\n" ::: "memory")
#define CP_WAIT0()  asm volatile("cp.async.wait_group 0;\n" ::: "memory")

__device__ __forceinline__ void ldmx4(uint32_t& r0, uint32_t& r1, uint32_t& r2,
                                      uint32_t& r3, uint32_t saddr) {
    asm volatile("ldmatrix.sync.aligned.m8n8.x4.shared.b16 {%0,%1,%2,%3}, [%4];"
                 : "=r"(r0), "=r"(r1), "=r"(r2), "=r"(r3) : "r"(saddr));
}
__device__ __forceinline__ void ldmx4t(uint32_t& r0, uint32_t& r1, uint32_t& r2,
                                       uint32_t& r3, uint32_t saddr) {
    asm volatile("ldmatrix.sync.aligned.m8n8.x4.trans.shared.b16 {%0,%1,%2,%3}, [%4];"
                 : "=r"(r0), "=r"(r1), "=r"(r2), "=r"(r3) : "r"(saddr));
}
__device__ __forceinline__ void ldmx2t(uint32_t& r0, uint32_t& r1, uint32_t saddr) {
    asm volatile("ldmatrix.sync.aligned.m8n8.x2.trans.shared.b16 {%0,%1}, [%2];"
                 : "=r"(r0), "=r"(r1) : "r"(saddr));
}

// ---------------------------------------------------------------------------
// rounding kernels (fp32 -> fp16 RNE)
// ---------------------------------------------------------------------------
__global__ void __launch_bounds__(256)
around(const float* __restrict__ A, __half* __restrict__ oh)
{
    int i = blockIdx.x * 256 + threadIdx.x;
    float4 v = ((const float4*)A)[i];
    ((uint2*)oh)[i] = make_uint2(packh(__float2half_rn(v.x), __float2half_rn(v.y)),
                                 packh(__float2half_rn(v.z), __float2half_rn(v.w)));
}
__global__ void __launch_bounds__(256)
wround4(const float* __restrict__ W0, const float* __restrict__ W1,
        const float* __restrict__ W2, const float* __restrict__ W3,
        __half* __restrict__ bhBase)
{
    __shared__ float t[32][33];
    const float* W = (blockIdx.z == 0) ? W0 : (blockIdx.z == 1) ? W1
                   : (blockIdx.z == 2) ? W2 : W3;
    __half* bh = bhBase + (size_t)blockIdx.z * ED * ED;
    int k0 = blockIdx.x * 32, n0 = blockIdx.y * 32;
    int tx = threadIdx.x, ty = threadIdx.y;            // (32, 8)
    #pragma unroll
    for (int i = 0; i < 4; i++)
        t[ty + 8 * i][tx] = W[(size_t)(k0 + ty + 8 * i) * ED + n0 + tx];
    __syncthreads();
    #pragma unroll
    for (int i = 0; i < 4; i++)
        bh[(size_t)(n0 + ty + 8 * i) * ED + k0 + tx] = __float2half_rn(t[tx][ty + 8 * i]);
}

// ---------------------------------------------------------------------------
// fp16 GEMM: 128x128 tile, k-chunk 64, 8 warps (2x4), warp tile 64x32.
// cp.async double buffer (dynamic smem 72KB), ldmatrix.x4 frag loads. Pitch 72.
// ---------------------------------------------------------------------------
#define GP   72
#define GSTG (128 * GP)
#define GEMM_SMEM (2 * 2 * GSTG * 2)   // 73728 bytes

#define GEMM_MAIN(A_, B_)                                                          \
    extern __shared__ __half hsm[];                                                \
    const int tid = threadIdx.x;                                                   \
    const int w = tid >> 5, lane = tid & 31, g = lane >> 2, t = lane & 3;          \
    const int wm = w >> 2, wn = w & 3;                                             \
    const int m0 = blockIdx.y * 128;                                               \
    const int nrow0 = blockIdx.x * 128;                                            \
    const uint32_t hsmu = (uint32_t)__cvta_generic_to_shared(hsm);                 \
    const uint32_t aoff = (uint32_t)(((lane & 15) * GP + (lane >> 4) * 8) * 2);    \
    const uint32_t boff = (uint32_t)((((lane & 7) + ((lane >> 4) << 3)) * GP +     \
                                      (((lane >> 3) & 1) * 8)) * 2);               \
    float acc[4][4][4] = {};                                                       \
    auto stage = [&](int c, int s) {                                               \
        __half* base = hsm + (size_t)s * 2 * GSTG;                                 \
        const int k0 = c * 64;                                                     \
        _Pragma("unroll")                                                          \
        for (int i = 0; i < 4; i++) {                                              \
            int id = i * 256 + tid;                                                \
            int r = id >> 3, c8 = (id & 7) << 3;                                   \
            cpa16(base + r * GP + c8,        A_ + (size_t)(m0 + r) * ED + k0 + c8);\
            cpa16(base + GSTG + r * GP + c8, B_ + (size_t)(nrow0 + r) * ED + k0 + c8);\
        }                                                                          \
        CP_COMMIT();                                                               \
    };                                                                             \
    stage(0, 0);                                                                   \
    int buf = 0;                                                                   \
    for (int c = 0; c < 16; c++) {                                                 \
        if (c + 1 < 16) { stage(c + 1, buf ^ 1); CP_WAIT1(); }                     \
        else            { CP_WAIT0(); }                                            \
        __syncthreads();                                                           \
        const uint32_t cAu = hsmu + (uint32_t)(buf * 4 * GSTG);                    \
        const uint32_t cBu = cAu + (uint32_t)(2 * GSTG);                           \
        _Pragma("unroll")                                                          \
        for (int ks = 0; ks < 4; ks++) {                                           \
            uint32_t af[4][4];                                                     \
            _Pragma("unroll")                                                      \
            for (int mt = 0; mt < 4; mt++)                                         \
                ldmx4(af[mt][0], af[mt][1], af[mt][2], af[mt][3],                  \
                      cAu + (uint32_t)((((wm * 64 + mt * 16) * GP) + ks * 16) * 2) \
                          + aoff);                                                 \
            uint32_t bf[4][2];                                                     \
            _Pragma("unroll")                                                      \
            for (int np = 0; np < 2; np++)                                         \
                ldmx4(bf[2 * np][0], bf[2 * np][1], bf[2 * np + 1][0],             \
                      bf[2 * np + 1][1],                                           \
                      cBu + (uint32_t)((((wn * 32 + np * 16) * GP) + ks * 16) * 2) \
                          + boff);                                                 \
            _Pragma("unroll")                                                      \
            for (int mt = 0; mt < 4; mt++)                                         \
                _Pragma("unroll")                                                  \
                for (int nc = 0; nc < 4; nc++)                                     \
                    mma16(acc[mt][nc], af[mt], bf[nc][0], bf[nc][1]);              \
        }                                                                          \
        __syncthreads();                                                           \
        buf ^= 1;                                                                  \
    }

// fused QKV: B packed [3072][1024]; seg 0=Q (xQSCALE, exp2 domain), 1=K, 2=V
__global__ void __launch_bounds__(256, 2)
gemm_qkv(const __half* __restrict__ A, const __half* __restrict__ B,
         const float* __restrict__ bq, const float* __restrict__ bk,
         const float* __restrict__ bv,
         __half* __restrict__ Qh, __half* __restrict__ Kh, __half* __restrict__ Vh)
{
    GEMM_MAIN(A, B)

    const int seg = blockIdx.x >> 3;
    const int ncol0 = (blockIdx.x & 7) * 128;
    const float* bias = (seg == 0) ? bq : (seg == 1) ? bk : bv;
    __half* O = (seg == 0) ? Qh : (seg == 1) ? Kh : Vh;
    const float sc = (seg == 0) ? QSCALE : 1.0f;

    #pragma unroll
    for (int mt = 0; mt < 4; mt++) {
        int row = m0 + wm * 64 + mt * 16 + g;
        #pragma unroll
        for (int nc = 0; nc < 4; nc++) {
            int col = ncol0 + wn * 32 + nc * 8 + 2 * t;
            float b0 = bias[col], b1 = bias[col + 1];
            *(uint32_t*)(O + (size_t)row * ED + col) =
                packh(__float2half_rn((acc[mt][nc][0] + b0) * sc),
                      __float2half_rn((acc[mt][nc][1] + b1) * sc));
            *(uint32_t*)(O + (size_t)(row + 8) * ED + col) =
                packh(__float2half_rn((acc[mt][nc][2] + b0) * sc),
                      __float2half_rn((acc[mt][nc][3] + b1) * sc));
        }
    }
}

// O projection: float out
__global__ void __launch_bounds__(256, 2)
gemm_o(const __half* __restrict__ A, const __half* __restrict__ B,
       const float* __restrict__ bias, float* __restrict__ out)
{
    GEMM_MAIN(A, B)

    #pragma unroll
    for (int mt = 0; mt < 4; mt++) {
        int row = m0 + wm * 64 + mt * 16 + g;
        #pragma unroll
        for (int nc = 0; nc < 4; nc++) {
            int col = nrow0 + wn * 32 + nc * 8 + 2 * t;
            float b0 = bias[col], b1 = bias[col + 1];
            *(float2*)(out + (size_t)row * ED + col) =
                make_float2(acc[mt][nc][0] + b0, acc[mt][nc][1] + b1);
            *(float2*)(out + (size_t)(row + 8) * ED + col) =
                make_float2(acc[mt][nc][2] + b0, acc[mt][nc][3] + b1);
        }
    }
}

// ---------------------------------------------------------------------------
// fp16 flash attention, exp2 domain, 2 CTAs/SM.
// P via h2exp2 (f16x2 MUFU). Row-sum l via ones-block mma (V cols 64..71,
// ALL ones -> every C-frag column holds the row sum -> lane-uniform l).
// ---------------------------------------------------------------------------
#define PH   72
#define HSTG (64 * PH)

__global__ void __launch_bounds__(256, 2)
attn_h(const __half* __restrict__ Q, const __half* __restrict__ K,
       const __half* __restrict__ V, const float* __restrict__ X,
       __half* __restrict__ CH)
{
    __shared__ __half asm_[4 * HSTG];       // 36864 B
    __half* sK = asm_;
    __half* sV = asm_ + 2 * HSTG;

    const int tid = threadIdx.x;
    const int w = tid >> 5, lane = tid & 31, g = lane >> 2, t = lane & 3;
    const int qt = blockIdx.x, h = blockIdx.y, b = blockIdx.z;
    const int qrow0 = b * SEQ + qt * 128;
    const int coff  = h * HD;

    // ldmatrix per-lane offsets (bytes)
    const int matq = lane >> 3;
    const uint32_t ldmoffV = (uint32_t)((((matq & 1) * 8 + (lane & 7)) * PH +
                                         (matq >> 1) * 8) * 2);          // V x4 trans
    const uint32_t ldmoffK = (uint32_t)((((lane & 7) + ((lane >> 4) << 3)) * PH +
                                         (((lane >> 3) & 1) * 8)) * 2);  // K x4 B-frag
    const uint32_t ldmoffL = (uint32_t)(((((lane >> 3) & 1) * 8 + (lane & 7)) * PH) * 2)
                             + 64 * 2;                                   // ones-block x2 trans
    const uint32_t sKu = (uint32_t)__cvta_generic_to_shared(sK);
    const uint32_t sVu = (uint32_t)__cvta_generic_to_shared(sV);

    // init V cols 64..71 in both buffers: ALL ones (row-sum via mma, lane-uniform)
    for (int i = tid; i < 2 * 64; i += 256) {
        int bf = i >> 6, r = i & 63;
        __half* dst = sV + bf * HSTG + r * PH + 64;
        #pragma unroll
        for (int j = 0; j < 8; j++) dst[j] = __float2half(1.0f);
    }

    uint32_t qf[4][4];
    {
        const int r0 = qrow0 + w * 16 + g;
        #pragma unroll
        for (int kc = 0; kc < 4; kc++) {
            int c0 = coff + kc * 16 + 2 * t;
            qf[kc][0] = *(const uint32_t*)(Q + (size_t)r0 * ED + c0);
            qf[kc][1] = *(const uint32_t*)(Q + (size_t)(r0 + 8) * ED + c0);
            qf[kc][2] = *(const uint32_t*)(Q + (size_t)r0 * ED + c0 + 8);
            qf[kc][3] = *(const uint32_t*)(Q + (size_t)(r0 + 8) * ED + c0 + 8);
        }
    }

    auto stage = [&](int kt, int s) {
        const int krow0 = b * SEQ + kt * 64;
        __half* dK = sK + s * HSTG;
        __half* dV = sV + s * HSTG;
        #pragma unroll
        for (int i = 0; i < 2; i++) {
            int id = i * 256 + tid;
            int r = id >> 3, c8 = (id & 7) << 3;
            cpa16(dK + r * PH + c8, K + (size_t)(krow0 + r) * ED + coff + c8);
            cpa16(dV + r * PH + c8, V + (size_t)(krow0 + r) * ED + coff + c8);
        }
        CP_COMMIT();
    };

    stage(0, 0);

    float m1 = -1e30f, m2 = -1e30f;
    float ol[4] = {};                        // [0]=l(row g), [2]=l(row g+8)
    float o[8][4] = {};

    int buf = 0;
    for (int kt = 0; kt < SEQ / 64; kt++) {
        if (kt + 1 < SEQ / 64) { stage(kt + 1, buf ^ 1); CP_WAIT1(); }
        else                   { CP_WAIT0(); }
        __syncthreads();

        const uint32_t cKu = sKu + (uint32_t)(buf * HSTG * 2);
        const uint32_t cVu = sVu + (uint32_t)(buf * HSTG * 2);

        // S = Q @ K^T
        float s[8][4] = {};
        #pragma unroll
        for (int kc = 0; kc < 4; kc++) {
            #pragma unroll
            for (int np = 0; np < 4; np++) {
                uint32_t b00, b01, b10, b11;
                ldmx4(b00, b01, b10, b11,
                      cKu + (uint32_t)((np * 16 * PH + kc * 16) * 2) + ldmoffK);
                mma16(s[2 * np],     qf[kc], b00, b01);
                mma16(s[2 * np + 1], qf[kc], b10, b11);
            }
        }

        // online softmax in exp2 domain (rows g, g+8; quad reduce for max)
        float tm1 = -1e30f, tm2 = -1e30f;
        #pragma unroll
        for (int nc = 0; nc < 8; nc++) {
            tm1 = fmaxf(tm1, fmaxf(s[nc][0], s[nc][1]));
            tm2 = fmaxf(tm2, fmaxf(s[nc][2], s[nc][3]));
        }
        tm1 = fmaxf(tm1, __shfl_xor_sync(0xffffffffu, tm1, 1));
        tm1 = fmaxf(tm1, __shfl_xor_sync(0xffffffffu, tm1, 2));
        tm2 = fmaxf(tm2, __shfl_xor_sync(0xffffffffu, tm2, 1));
        tm2 = fmaxf(tm2, __shfl_xor_sync(0xffffffffu, tm2, 2));

        float mn1 = fmaxf(m1, tm1), mn2 = fmaxf(m2, tm2);
        float c1 = exp2f(m1 - mn1), c2 = exp2f(m2 - mn2);
        m1 = mn1; m2 = mn2;

        // P in fp16 via packed MUFU exp2 (half the MUFU ops, no pack step)
        uint32_t p0[8], p1[8];
        #pragma unroll
        for (int nc = 0; nc < 8; nc++) {
            __half2 e01 = h2exp2(__floats2half2_rn(s[nc][0] - mn1, s[nc][1] - mn1));
            __half2 e23 = h2exp2(__floats2half2_rn(s[nc][2] - mn2, s[nc][3] - mn2));
            p0[nc] = *(uint32_t*)&e01;
            p1[nc] = *(uint32_t*)&e23;
        }

        // rescale running O and l
        ol[0] *= c1; ol[2] *= c2;
        #pragma unroll
        for (int nc = 0; nc < 8; nc++) {
            o[nc][0] *= c1; o[nc][1] *= c1;
            o[nc][2] *= c2; o[nc][3] *= c2;
        }

        // O += P @ V ; l += P @ ones (V ones-block)
        #pragma unroll
        for (int kc = 0; kc < 4; kc++) {
            uint32_t a[4] = { p0[2 * kc], p1[2 * kc], p0[2 * kc + 1], p1[2 * kc + 1] };
            uint32_t lb0, lb1;
            ldmx2t(lb0, lb1, cVu + (uint32_t)((kc * 16 * PH) * 2) + ldmoffL);
            mma16(ol, a, lb0, lb1);
            #pragma unroll
            for (int np = 0; np < 4; np++) {
                uint32_t r0, r1, r2, r3;
                ldmx4t(r0, r1, r2, r3,
                       cVu + (uint32_t)((kc * 16 * PH + np * 16) * 2) + ldmoffV);
                mma16(o[2 * np],     a, r0, r1);
                mma16(o[2 * np + 1], a, r2, r3);
            }
        }

        __syncthreads();
        buf ^= 1;
    }

    const float i1 = 1.f / ol[0], i2 = 1.f / ol[2];
    const int r0 = qrow0 + w * 16 + g;
    #pragma unroll
    for (int nc = 0; nc < 8; nc++) {
        int col = coff + nc * 8 + 2 * t;
        float2 x0 = *(const float2*)(X + (size_t)r0 * ED + col);
        float2 x1 = *(const float2*)(X + (size_t)(r0 + 8) * ED + col);
        *(uint32_t*)(CH + (size_t)r0 * ED + col) =
            packh(__float2half_rn(o[nc][0] * i1 + x0.x),
                  __float2half_rn(o[nc][1] * i1 + x0.y));
        *(uint32_t*)(CH + (size_t)(r0 + 8) * ED + col) =
            packh(__float2half_rn(o[nc][2] * i2 + x1.x),
                  __float2half_rn(o[nc][3] * i2 + x1.y));
    }
}

// ---------------------------------------------------------------------------
extern "C" void kernel_launch(void* const* d_in, const int* in_sizes, int n_in,
                              void* d_out, int out_size)
{
    const float* x  = (const float*)d_in[0];
    const float* wq = (const float*)d_in[1];
    const float* bq = (const float*)d_in[2];
    const float* wk = (const float*)d_in[3];
    const float* bk = (const float*)d_in[4];
    const float* wv = (const float*)d_in[5];
    const float* bv = (const float*)d_in[6];
    const float* wo = (const float*)d_in[7];
    const float* bo = (const float*)d_in[8];
    float* out = (float*)d_out;

    __half *Qh, *Kh, *Vh, *xh, *ch, *wh;
    cudaGetSymbolAddress((void**)&Qh, g_Qh);
    cudaGetSymbolAddress((void**)&Kh, g_Kh);
    cudaGetSymbolAddress((void**)&Vh, g_Vh);
    cudaGetSymbolAddress((void**)&xh, g_xh);
    cudaGetSymbolAddress((void**)&ch, g_ch);
    cudaGetSymbolAddress((void**)&wh, g_wh);

    cudaFuncSetAttribute(gemm_qkv, cudaFuncAttributeMaxDynamicSharedMemorySize, GEMM_SMEM);
    cudaFuncSetAttribute(gemm_o,   cudaFuncAttributeMaxDynamicSharedMemorySize, GEMM_SMEM);

    around<<<MTOT * ED / 1024, 256>>>(x, xh);
    wround4<<<dim3(ED / 32, ED / 32, 4), dim3(32, 8)>>>(wq, wk, wv, wo, wh);

    gemm_qkv<<<dim3(3 * ED / 128, MTOT / 128), 256, GEMM_SMEM>>>(xh, wh, bq, bk, bv,
                                                                 Qh, Kh, Vh);

    attn_h<<<dim3(SEQ / 128, NH, BATCH), 256>>>(Qh, Kh, Vh, x, ch);

    gemm_o<<<dim3(ED / 128, MTOT / 128), 256, GEMM_SMEM>>>(ch, wh + 3 * (size_t)ED * ED,
                                                           bo, out);
}